// round 6
// baseline (speedup 1.0000x reference)
#include <cuda_runtime.h>
#include <cstdint>

// Problem dims
#define BATCH 64
#define N1    1152
#define PDIM  8
#define N2    128
#define DDIM  16
// derived
#define KX    (N1*PDIM)          // 9216
#define BI    (BATCH*N1)         // 73728
#define EPSF  1.1920929e-7f

// tiling
#define SLICES 6
#define ISL    (N1/SLICES)       // 192 i's per slice
#define IL     8                 // i's per smem tile
#define TILES  (ISL/IL)          // 24
#define XROW   68                // padded x row (64 + 4)

typedef unsigned long long ull;

// ---------------- scratch (device globals; no allocations) ----------------
__device__ float g_v0[N2 * BATCH * DDIM];              // [n][b][d]
__device__ float g_raw[(size_t)N2 * N1 * BATCH];       // [n][i][b]  37.7 MB
__device__ float g_inv[BI];
__device__ float g_part[(size_t)SLICES * N2 * BATCH * DDIM]; // [s][n][b][d]

// ---------------- packed f32x2 helpers ----------------
__device__ __forceinline__ ull ffma2(ull a, ull b, ull c) {
    ull d;
    asm("fma.rn.f32x2 %0, %1, %2, %3;" : "=l"(d) : "l"(a), "l"(b), "l"(c));
    return d;
}
__device__ __forceinline__ ull fmul2(ull a, ull b) {
    ull d;
    asm("mul.rn.f32x2 %0, %1, %2;" : "=l"(d) : "l"(a), "l"(b));
    return d;
}
__device__ __forceinline__ ull pack2(float lo, float hi) {
    ull r;
    asm("mov.b64 %0, {%1, %2};" : "=l"(r) : "f"(lo), "f"(hi));
    return r;
}
__device__ __forceinline__ float hadd2(ull v) {
    float lo, hi;
    asm("mov.b64 {%0, %1}, %2;" : "=f"(lo), "=f"(hi) : "l"(v));
    return lo + hi;
}

// ---------------- cp.async helpers ----------------
__device__ __forceinline__ void cpa16(uint32_t s, const float* g) {
    asm volatile("cp.async.cg.shared.global [%0], [%1], 16;" :: "r"(s), "l"(g));
}
__device__ __forceinline__ void cpcommit() {
    asm volatile("cp.async.commit_group;");
}

// ---------------- async tile loader ----------------
// ws tile: [IL=8 il][128] floats = W[i0+il, n, d, p] (linear d*8+p)       4 KB
// xs tile: [64 b][XROW=68] floats, x[b, i0+il, p] at b*68 + il*8 + p    17 KB
__device__ __forceinline__ void tile_load(uint32_t ws_s, uint32_t xs_s,
                                          const float* __restrict__ x,
                                          const float* __restrict__ W,
                                          int n, int i0, int t) {
    {   // W: 256 float4, one per thread
        int il = t >> 5, c4 = t & 31;
        cpa16(ws_s + (uint32_t)(il * 128 + c4 * 4) * 4,
              W + (size_t)(i0 + il) * (N2 * DDIM * PDIM)
                + (size_t)n * (DDIM * PDIM) + c4 * 4);
    }
#pragma unroll
    for (int k = 0; k < 4; k++) {   // x: 1024 float4, 4 per thread
        int f4 = t + k * 256;
        int bb = f4 >> 4, r4 = f4 & 15;
        cpa16(xs_s + (uint32_t)(bb * XROW + r4 * 4) * 4,
              x + (size_t)bb * KX + i0 * PDIM + r4 * 4);
    }
}

// =====================================================================
// K1 partial: part[s][n][b][d] = sum_{i in slice, p} W[i,n,d,p] x[b,i,p]
// 256 thr: warp w (0..7): b = lane + 32*(w>>2); il in {w&3, (w&3)+4}
// =====================================================================
__global__ void __launch_bounds__(256, 2) cap_k1p(const float* __restrict__ x,
                                                  const float* __restrict__ W) {
    __shared__ float ws[2][IL * 128];
    __shared__ float xs[2][BATCH * XROW];
    const int n = blockIdx.x, s = blockIdx.y;
    const int t = threadIdx.x, w = t >> 5, lane = t & 31;
    const int il0 = w & 3;
    const int b = lane + 32 * (w >> 2);
    const int ib = s * ISL;
    uint32_t wss[2] = { (uint32_t)__cvta_generic_to_shared(&ws[0][0]),
                        (uint32_t)__cvta_generic_to_shared(&ws[1][0]) };
    uint32_t xss[2] = { (uint32_t)__cvta_generic_to_shared(&xs[0][0]),
                        (uint32_t)__cvta_generic_to_shared(&xs[1][0]) };

    ull acc[16];
#pragma unroll
    for (int d = 0; d < 16; d++) acc[d] = 0ULL;

    tile_load(wss[0], xss[0], x, W, n, ib, t);
    cpcommit();

    for (int tt = 0; tt < TILES; tt++) {
        if (tt + 1 < TILES) {
            tile_load(wss[(tt + 1) & 1], xss[(tt + 1) & 1], x, W, n,
                      ib + (tt + 1) * IL, t);
            cpcommit();
            asm volatile("cp.async.wait_group 1;");
        } else {
            asm volatile("cp.async.wait_group 0;");
        }
        __syncthreads();
        const float* wsb = ws[tt & 1];
        const float* xsb = xs[tt & 1];
#pragma unroll
        for (int h = 0; h < 2; h++) {
            const int il = il0 + 4 * h;
            ulonglong2 x01 = *(const ulonglong2*)&xsb[b * XROW + il * 8];
            ulonglong2 x23 = *(const ulonglong2*)&xsb[b * XROW + il * 8 + 4];
            const ulonglong2* wv = (const ulonglong2*)&wsb[il * 128];
#pragma unroll
            for (int d = 0; d < 16; d++) {
                ulonglong2 w01 = wv[2 * d], w23 = wv[2 * d + 1];
                acc[d] = ffma2(w01.x, x01.x, acc[d]);
                acc[d] = ffma2(w01.y, x01.y, acc[d]);
                acc[d] = ffma2(w23.x, x23.x, acc[d]);
                acc[d] = ffma2(w23.y, x23.y, acc[d]);
            }
        }
        __syncthreads();
    }

    // cross-warp reduce into xs[0] (free now): red[w][lane][16]
    float* red = &xs[0][0];
#pragma unroll
    for (int d = 0; d < 16; d++)
        red[w * 512 + lane * 16 + d] = hadd2(acc[d]);
    __syncthreads();
    {
        int bb = t >> 2, dq = t & 3;
        int sub2 = bb >> 5, bl = bb & 31;
        float4 v = make_float4(0.f, 0.f, 0.f, 0.f);
#pragma unroll
        for (int k = 0; k < 4; k++) {
            const float* r = &red[(sub2 * 4 + k) * 512 + bl * 16 + dq * 4];
            v.x += r[0]; v.y += r[1]; v.z += r[2]; v.w += r[3];
        }
        *(float4*)&g_part[(((size_t)s * N2 + n) * BATCH + bb) * DDIM + dq * 4] = v;
    }
}

// =====================================================================
// K1 reduce: v0[n][b][d] = squash( (1/128) * sum_s part )
// =====================================================================
__global__ void __launch_bounds__(64) cap_k1r() {
    const int n = blockIdx.x, b = threadIdx.x;
    float sv[16];
#pragma unroll
    for (int d = 0; d < 16; d++) sv[d] = 0.f;
    for (int sl = 0; sl < SLICES; sl++) {
        const float4* p = (const float4*)&g_part[(((size_t)sl * N2 + n) * BATCH + b) * DDIM];
#pragma unroll
        for (int q = 0; q < 4; q++) {
            float4 v = p[q];
            sv[4 * q + 0] += v.x; sv[4 * q + 1] += v.y;
            sv[4 * q + 2] += v.z; sv[4 * q + 3] += v.w;
        }
    }
    float sq = 0.f;
#pragma unroll
    for (int d = 0; d < 16; d++) { sv[d] *= (1.f / 128.f); sq += sv[d] * sv[d]; }
    float f = sq / ((1.f + sq) * sqrtf(sq + EPSF));
    float4* o = (float4*)&g_v0[((size_t)n * BATCH + b) * DDIM];
#pragma unroll
    for (int q = 0; q < 4; q++)
        o[q] = make_float4(f * sv[4 * q], f * sv[4 * q + 1],
                           f * sv[4 * q + 2], f * sv[4 * q + 3]);
}

// =====================================================================
// K2: raw[n][i][b] = sum_p x[b,i,p] * ( sum_d v0[n,b,d] W[i,n,d,p] )
// =====================================================================
__global__ void __launch_bounds__(256, 2) cap_k2(const float* __restrict__ x,
                                                 const float* __restrict__ W) {
    __shared__ float ws[2][IL * 128];
    __shared__ float xs[2][BATCH * XROW];
    const int n = blockIdx.x, s = blockIdx.y;
    const int t = threadIdx.x, w = t >> 5, lane = t & 31;
    const int il0 = w & 3;
    const int b = lane + 32 * (w >> 2);
    const int ib = s * ISL;
    uint32_t wss[2] = { (uint32_t)__cvta_generic_to_shared(&ws[0][0]),
                        (uint32_t)__cvta_generic_to_shared(&ws[1][0]) };
    uint32_t xss[2] = { (uint32_t)__cvta_generic_to_shared(&xs[0][0]),
                        (uint32_t)__cvta_generic_to_shared(&xs[1][0]) };

    ull u[16];
    {
        const float* v0p = &g_v0[((size_t)n * BATCH + b) * DDIM];
#pragma unroll
        for (int q = 0; q < 4; q++) {
            float4 vv = *(const float4*)&v0p[q * 4];
            u[q * 4 + 0] = pack2(vv.x, vv.x);
            u[q * 4 + 1] = pack2(vv.y, vv.y);
            u[q * 4 + 2] = pack2(vv.z, vv.z);
            u[q * 4 + 3] = pack2(vv.w, vv.w);
        }
    }

    tile_load(wss[0], xss[0], x, W, n, ib, t);
    cpcommit();

    for (int tt = 0; tt < TILES; tt++) {
        if (tt + 1 < TILES) {
            tile_load(wss[(tt + 1) & 1], xss[(tt + 1) & 1], x, W, n,
                      ib + (tt + 1) * IL, t);
            cpcommit();
            asm volatile("cp.async.wait_group 1;");
        } else {
            asm volatile("cp.async.wait_group 0;");
        }
        __syncthreads();
        const float* wsb = ws[tt & 1];
        const float* xsb = xs[tt & 1];
        const int i0 = ib + tt * IL;
#pragma unroll
        for (int h = 0; h < 2; h++) {
            const int il = il0 + 4 * h;
            const int i = i0 + il;
            const ulonglong2* wv = (const ulonglong2*)&wsb[il * 128];
            ull t0 = 0, t1 = 0, t2 = 0, t3 = 0;
#pragma unroll
            for (int d = 0; d < 16; d++) {
                ulonglong2 w01 = wv[2 * d], w23 = wv[2 * d + 1];
                t0 = ffma2(u[d], w01.x, t0);
                t1 = ffma2(u[d], w01.y, t1);
                t2 = ffma2(u[d], w23.x, t2);
                t3 = ffma2(u[d], w23.y, t3);
            }
            ulonglong2 x01 = *(const ulonglong2*)&xsb[b * XROW + il * 8];
            ulonglong2 x23 = *(const ulonglong2*)&xsb[b * XROW + il * 8 + 4];
            ull r = fmul2(x01.x, t0);
            r = ffma2(x01.y, t1, r);
            r = ffma2(x23.x, t2, r);
            r = ffma2(x23.y, t3, r);
            g_raw[(size_t)n * BI + (size_t)i * BATCH + b] = hadd2(r);
        }
        __syncthreads();
    }
}

// =====================================================================
// K3: per (b,i): inv = 1 / sum_n exp(raw)   (shift-free softmax; raw is
// bounded ~|pred||v0| ≲ 30, well inside fp32 exp range; softmax is
// shift-invariant so result matches reference)
// =====================================================================
__global__ void __launch_bounds__(256) cap_k3() {
    const int j = blockIdx.x * 256 + threadIdx.x;   // j = i*64 + b
    float s = 0.f;
#pragma unroll 16
    for (int n = 0; n < N2; n++)
        s += __expf(g_raw[(size_t)n * BI + j]);
    g_inv[j] = 1.f / s;
}

// =====================================================================
// K4 partial: part[s][n][b][d] = sum_{i in slice} c[b,i,n] * pred[b,i,n,d]
// c = exp(raw) * inv
// =====================================================================
__global__ void __launch_bounds__(256, 2) cap_k4p(const float* __restrict__ x,
                                                  const float* __restrict__ W) {
    __shared__ float ws[2][IL * 128];
    __shared__ float xs[2][BATCH * XROW];
    const int n = blockIdx.x, s = blockIdx.y;
    const int t = threadIdx.x, w = t >> 5, lane = t & 31;
    const int il0 = w & 3;
    const int b = lane + 32 * (w >> 2);
    const int ib = s * ISL;
    uint32_t wss[2] = { (uint32_t)__cvta_generic_to_shared(&ws[0][0]),
                        (uint32_t)__cvta_generic_to_shared(&ws[1][0]) };
    uint32_t xss[2] = { (uint32_t)__cvta_generic_to_shared(&xs[0][0]),
                        (uint32_t)__cvta_generic_to_shared(&xs[1][0]) };

    ull acc[16];
#pragma unroll
    for (int d = 0; d < 16; d++) acc[d] = 0ULL;

    tile_load(wss[0], xss[0], x, W, n, ib, t);
    cpcommit();

    for (int tt = 0; tt < TILES; tt++) {
        if (tt + 1 < TILES) {
            tile_load(wss[(tt + 1) & 1], xss[(tt + 1) & 1], x, W, n,
                      ib + (tt + 1) * IL, t);
            cpcommit();
            asm volatile("cp.async.wait_group 1;");
        } else {
            asm volatile("cp.async.wait_group 0;");
        }
        __syncthreads();
        const float* wsb = ws[tt & 1];
        const float* xsb = xs[tt & 1];
        const int i0 = ib + tt * IL;
#pragma unroll
        for (int h = 0; h < 2; h++) {
            const int il = il0 + 4 * h;
            const int i = i0 + il;
            const int j = i * BATCH + b;
            float c = __expf(g_raw[(size_t)n * BI + j]) * g_inv[j];
            ull c2 = pack2(c, c);
            ulonglong2 x01 = *(const ulonglong2*)&xsb[b * XROW + il * 8];
            ulonglong2 x23 = *(const ulonglong2*)&xsb[b * XROW + il * 8 + 4];
            ull xa0 = fmul2(c2, x01.x), xa1 = fmul2(c2, x01.y);
            ull xa2 = fmul2(c2, x23.x), xa3 = fmul2(c2, x23.y);
            const ulonglong2* wv = (const ulonglong2*)&wsb[il * 128];
#pragma unroll
            for (int d = 0; d < 16; d++) {
                ulonglong2 w01 = wv[2 * d], w23 = wv[2 * d + 1];
                acc[d] = ffma2(w01.x, xa0, acc[d]);
                acc[d] = ffma2(w01.y, xa1, acc[d]);
                acc[d] = ffma2(w23.x, xa2, acc[d]);
                acc[d] = ffma2(w23.y, xa3, acc[d]);
            }
        }
        __syncthreads();
    }

    float* red = &xs[0][0];
#pragma unroll
    for (int d = 0; d < 16; d++)
        red[w * 512 + lane * 16 + d] = hadd2(acc[d]);
    __syncthreads();
    {
        int bb = t >> 2, dq = t & 3;
        int sub2 = bb >> 5, bl = bb & 31;
        float4 v = make_float4(0.f, 0.f, 0.f, 0.f);
#pragma unroll
        for (int k = 0; k < 4; k++) {
            const float* r = &red[(sub2 * 4 + k) * 512 + bl * 16 + dq * 4];
            v.x += r[0]; v.y += r[1]; v.z += r[2]; v.w += r[3];
        }
        *(float4*)&g_part[(((size_t)s * N2 + n) * BATCH + bb) * DDIM + dq * 4] = v;
    }
}

// =====================================================================
// K4 reduce: out[b][n][d] = squash_d( sum_s part[s][n][b][d] )
// =====================================================================
__global__ void __launch_bounds__(64) cap_k4r(float* __restrict__ out) {
    const int n = blockIdx.x, b = threadIdx.x;
    float sv[16];
#pragma unroll
    for (int d = 0; d < 16; d++) sv[d] = 0.f;
    for (int sl = 0; sl < SLICES; sl++) {
        const float4* p = (const float4*)&g_part[(((size_t)sl * N2 + n) * BATCH + b) * DDIM];
#pragma unroll
        for (int q = 0; q < 4; q++) {
            float4 v = p[q];
            sv[4 * q + 0] += v.x; sv[4 * q + 1] += v.y;
            sv[4 * q + 2] += v.z; sv[4 * q + 3] += v.w;
        }
    }
    float sq = 0.f;
#pragma unroll
    for (int d = 0; d < 16; d++) sq += sv[d] * sv[d];
    float f = sq / ((1.f + sq) * sqrtf(sq + EPSF));
    float4* o = (float4*)&out[((size_t)b * N2 + n) * DDIM];
#pragma unroll
    for (int q = 0; q < 4; q++)
        o[q] = make_float4(f * sv[4 * q], f * sv[4 * q + 1],
                           f * sv[4 * q + 2], f * sv[4 * q + 3]);
}

// =====================================================================
extern "C" void kernel_launch(void* const* d_in, const int* in_sizes, int n_in,
                              void* d_out, int out_size) {
    const float* x = (const float*)d_in[0];
    const float* W = (const float*)d_in[1];
    if (n_in >= 2 && in_sizes[0] > in_sizes[1]) {
        const float* tmp = x; x = W; W = tmp;
    }
    float* out = (float*)d_out;

    dim3 g(N2, SLICES);
    cap_k1p<<<g, 256>>>(x, W);
    cap_k1r<<<N2, 64>>>();
    cap_k2 <<<g, 256>>>(x, W);
    cap_k3 <<<BI / 256, 256>>>();
    cap_k4p<<<g, 256>>>(x, W);
    cap_k4r<<<N2, 64>>>(out);
}

// round 7
// speedup vs baseline: 1.1204x; 1.1204x over previous
#include <cuda_runtime.h>
#include <cstdint>

// Problem dims
#define BATCH 64
#define N1    1152
#define PDIM  8
#define N2    128
#define DDIM  16
#define KX    (N1*PDIM)          // 9216
#define BI    (BATCH*N1)         // 73728
#define EPSF  1.1920929e-7f

// tiling
#define SLICES 6
#define ISL    (N1/SLICES)       // 192 i's per slice
#define IL     8                 // i's per smem tile (= warps per block)
#define TILES  (ISL/IL)          // 24
#define BH     32                // batch-half per CTA
#define XROW   68                // padded x row (64 + 4)
#define WS_F   (IL*128)          // 1024 floats per W stage
#define XS_F   (BH*XROW)         // 2176 floats per x stage
#define STAGE_F (WS_F + XS_F)    // 3200 floats = 12.5 KB
#define NSTAGE 3

typedef unsigned long long ull;

// ---------------- scratch (device globals; no allocations) ----------------
__device__ float g_v0[N2 * BATCH * DDIM];              // [n][b][d]
__device__ float g_raw[(size_t)N2 * N1 * BATCH];       // [n][i][b]  37.7 MB
__device__ float g_inv[BI];
__device__ float g_part[(size_t)SLICES * N2 * BATCH * DDIM]; // [s][n][b][d]

// ---------------- packed f32x2 helpers ----------------
__device__ __forceinline__ ull ffma2(ull a, ull b, ull c) {
    ull d;
    asm("fma.rn.f32x2 %0, %1, %2, %3;" : "=l"(d) : "l"(a), "l"(b), "l"(c));
    return d;
}
__device__ __forceinline__ ull fmul2(ull a, ull b) {
    ull d;
    asm("mul.rn.f32x2 %0, %1, %2;" : "=l"(d) : "l"(a), "l"(b));
    return d;
}
__device__ __forceinline__ ull pack2(float lo, float hi) {
    ull r;
    asm("mov.b64 %0, {%1, %2};" : "=l"(r) : "f"(lo), "f"(hi));
    return r;
}
__device__ __forceinline__ float hadd2(ull v) {
    float lo, hi;
    asm("mov.b64 {%0, %1}, %2;" : "=f"(lo), "=f"(hi) : "l"(v));
    return lo + hi;
}

// ---------------- cp.async helpers ----------------
__device__ __forceinline__ void cpa16(uint32_t s, const float* g) {
    asm volatile("cp.async.cg.shared.global [%0], [%1], 16;" :: "r"(s), "l"(g));
}
__device__ __forceinline__ void cpcommit() {
    asm volatile("cp.async.commit_group;");
}

// ---------------- async tile loader (3 cp.async / thread) ----------------
// stage layout: [WS_F floats of W tile][XS_F floats of x tile]
// W tile:  [8 il][128]  = W[i0+il, n, d, p] (linear d*8+p)
// x tile:  [32 bb][68]  = x[half*32+bb, i0+il, p] at bb*68 + il*8 + p
__device__ __forceinline__ void tile_load(uint32_t stage_s,
                                          const float* __restrict__ x,
                                          const float* __restrict__ W,
                                          int n, int i0, int bbase, int t) {
    {   // W: 256 float4, one per thread
        int il = t >> 5, c4 = t & 31;
        cpa16(stage_s + (uint32_t)(il * 128 + c4 * 4) * 4,
              W + (size_t)(i0 + il) * (N2 * DDIM * PDIM)
                + (size_t)n * (DDIM * PDIM) + c4 * 4);
    }
    uint32_t xs_s = stage_s + WS_F * 4;
#pragma unroll
    for (int k = 0; k < 2; k++) {   // x: 512 float4, 2 per thread
        int f4 = t + k * 256;
        int bb = f4 >> 4, r4 = f4 & 15;
        cpa16(xs_s + (uint32_t)(bb * XROW + r4 * 4) * 4,
              x + (size_t)(bbase + bb) * KX + i0 * PDIM + r4 * 4);
    }
}

// =====================================================================
// K1 partial: part[s][n][bg][d] += sum_{i in slice, p} W[i,n,d,p] x[bg,i,p]
// warp w -> il=w; lane -> bb; bg = half*32 + bb
// =====================================================================
__global__ void __launch_bounds__(256, 3) cap_k1p(const float* __restrict__ x,
                                                  const float* __restrict__ W) {
    __shared__ float sm[NSTAGE * STAGE_F];
    const int n = blockIdx.x, s = blockIdx.y, half = blockIdx.z;
    const int t = threadIdx.x, w = t >> 5, lane = t & 31;
    const int ib = s * ISL;
    const int bbase = half * BH;
    const uint32_t sbase = (uint32_t)__cvta_generic_to_shared(sm);

    ull acc[16];
#pragma unroll
    for (int d = 0; d < 16; d++) acc[d] = 0ULL;

    tile_load(sbase, x, W, n, ib, bbase, t);               cpcommit();
    tile_load(sbase + STAGE_F * 4, x, W, n, ib + IL, bbase, t); cpcommit();

    for (int tt = 0; tt < TILES; tt++) {
        asm volatile("cp.async.wait_group 1;");
        __syncthreads();
        const int buf = tt % NSTAGE;
        const float* wsb = sm + buf * STAGE_F;
        const float* xsb = wsb + WS_F;

        ulonglong2 x01 = *(const ulonglong2*)&xsb[lane * XROW + w * 8];
        ulonglong2 x23 = *(const ulonglong2*)&xsb[lane * XROW + w * 8 + 4];
        const ulonglong2* wv = (const ulonglong2*)&wsb[w * 128];
#pragma unroll
        for (int d = 0; d < 16; d++) {
            ulonglong2 w01 = wv[2 * d], w23 = wv[2 * d + 1];
            acc[d] = ffma2(w01.x, x01.x, acc[d]);
            acc[d] = ffma2(w01.y, x01.y, acc[d]);
            acc[d] = ffma2(w23.x, x23.x, acc[d]);
            acc[d] = ffma2(w23.y, x23.y, acc[d]);
        }

        if (tt + 2 < TILES)
            tile_load(sbase + ((tt + 2) % NSTAGE) * STAGE_F * 4, x, W, n,
                      ib + (tt + 2) * IL, bbase, t);
        cpcommit();   // uniform group count (possibly empty)
    }

    __syncthreads();
    float* red = sm;                     // [8 w][32 b][16 d] = 16 KB
#pragma unroll
    for (int d = 0; d < 16; d++)
        red[w * 512 + lane * 16 + d] = hadd2(acc[d]);
    __syncthreads();
    if (t < 128) {
        int bb = t >> 2, dq = t & 3;
        float4 v = make_float4(0.f, 0.f, 0.f, 0.f);
#pragma unroll
        for (int k = 0; k < 8; k++) {
            const float* r = &red[k * 512 + bb * 16 + dq * 4];
            v.x += r[0]; v.y += r[1]; v.z += r[2]; v.w += r[3];
        }
        *(float4*)&g_part[(((size_t)s * N2 + n) * BATCH + bbase + bb) * DDIM + dq * 4] = v;
    }
}

// =====================================================================
// K1 reduce: v0[n][b][d] = squash( (1/128) * sum_s part )
// =====================================================================
__global__ void __launch_bounds__(64) cap_k1r() {
    const int n = blockIdx.x, b = threadIdx.x;
    float sv[16];
#pragma unroll
    for (int d = 0; d < 16; d++) sv[d] = 0.f;
    for (int sl = 0; sl < SLICES; sl++) {
        const float4* p = (const float4*)&g_part[(((size_t)sl * N2 + n) * BATCH + b) * DDIM];
#pragma unroll
        for (int q = 0; q < 4; q++) {
            float4 v = p[q];
            sv[4 * q + 0] += v.x; sv[4 * q + 1] += v.y;
            sv[4 * q + 2] += v.z; sv[4 * q + 3] += v.w;
        }
    }
    float sq = 0.f;
#pragma unroll
    for (int d = 0; d < 16; d++) { sv[d] *= (1.f / 128.f); sq += sv[d] * sv[d]; }
    float f = sq / ((1.f + sq) * sqrtf(sq + EPSF));
    float4* o = (float4*)&g_v0[((size_t)n * BATCH + b) * DDIM];
#pragma unroll
    for (int q = 0; q < 4; q++)
        o[q] = make_float4(f * sv[4 * q], f * sv[4 * q + 1],
                           f * sv[4 * q + 2], f * sv[4 * q + 3]);
}

// =====================================================================
// K2: raw[n][i][bg] = sum_p x[bg,i,p] * ( sum_d v0[n,bg,d] W[i,n,d,p] )
// warp w -> il=w (i = i0+w); lane -> bb
// =====================================================================
__global__ void __launch_bounds__(256, 3) cap_k2(const float* __restrict__ x,
                                                 const float* __restrict__ W) {
    __shared__ float sm[NSTAGE * STAGE_F];
    const int n = blockIdx.x, s = blockIdx.y, half = blockIdx.z;
    const int t = threadIdx.x, w = t >> 5, lane = t & 31;
    const int ib = s * ISL;
    const int bbase = half * BH;
    const int bg = bbase + lane;
    const uint32_t sbase = (uint32_t)__cvta_generic_to_shared(sm);

    float uf[16];
    {
        const float4* v0p = (const float4*)&g_v0[((size_t)n * BATCH + bg) * DDIM];
#pragma unroll
        for (int q = 0; q < 4; q++) {
            float4 vv = v0p[q];
            uf[q * 4 + 0] = vv.x; uf[q * 4 + 1] = vv.y;
            uf[q * 4 + 2] = vv.z; uf[q * 4 + 3] = vv.w;
        }
    }

    tile_load(sbase, x, W, n, ib, bbase, t);               cpcommit();
    tile_load(sbase + STAGE_F * 4, x, W, n, ib + IL, bbase, t); cpcommit();

    for (int tt = 0; tt < TILES; tt++) {
        asm volatile("cp.async.wait_group 1;");
        __syncthreads();
        const int buf = tt % NSTAGE;
        const float* wsb = sm + buf * STAGE_F;
        const float* xsb = wsb + WS_F;
        const int i = ib + tt * IL + w;

        const ulonglong2* wv = (const ulonglong2*)&wsb[w * 128];
        ull t0 = 0, t1 = 0, t2 = 0, t3 = 0;
#pragma unroll
        for (int d = 0; d < 16; d++) {
            ull ud = pack2(uf[d], uf[d]);
            ulonglong2 w01 = wv[2 * d], w23 = wv[2 * d + 1];
            t0 = ffma2(ud, w01.x, t0);
            t1 = ffma2(ud, w01.y, t1);
            t2 = ffma2(ud, w23.x, t2);
            t3 = ffma2(ud, w23.y, t3);
        }
        ulonglong2 x01 = *(const ulonglong2*)&xsb[lane * XROW + w * 8];
        ulonglong2 x23 = *(const ulonglong2*)&xsb[lane * XROW + w * 8 + 4];
        ull r = fmul2(x01.x, t0);
        r = ffma2(x01.y, t1, r);
        r = ffma2(x23.x, t2, r);
        r = ffma2(x23.y, t3, r);
        g_raw[(size_t)n * BI + (size_t)i * BATCH + bg] = hadd2(r);

        if (tt + 2 < TILES)
            tile_load(sbase + ((tt + 2) % NSTAGE) * STAGE_F * 4, x, W, n,
                      ib + (tt + 2) * IL, bbase, t);
        cpcommit();
    }
}

// =====================================================================
// K3: per (b,i): inv = 1 / sum_n exp(raw)   (shift-free; raw bounded,
// softmax shift-invariant)
// =====================================================================
__global__ void __launch_bounds__(256) cap_k3() {
    const int j = blockIdx.x * 256 + threadIdx.x;   // j = i*64 + b
    float s = 0.f;
#pragma unroll 16
    for (int n = 0; n < N2; n++)
        s += __expf(g_raw[(size_t)n * BI + j]);
    g_inv[j] = 1.f / s;
}

// =====================================================================
// K4 partial: part[s][n][bg][d] = sum_{i in slice} c[bg,i,n]*pred[bg,i,n,d]
// c = exp(raw) * inv
// =====================================================================
__global__ void __launch_bounds__(256, 3) cap_k4p(const float* __restrict__ x,
                                                  const float* __restrict__ W) {
    __shared__ float sm[NSTAGE * STAGE_F];
    const int n = blockIdx.x, s = blockIdx.y, half = blockIdx.z;
    const int t = threadIdx.x, w = t >> 5, lane = t & 31;
    const int ib = s * ISL;
    const int bbase = half * BH;
    const int bg = bbase + lane;
    const uint32_t sbase = (uint32_t)__cvta_generic_to_shared(sm);

    ull acc[16];
#pragma unroll
    for (int d = 0; d < 16; d++) acc[d] = 0ULL;

    tile_load(sbase, x, W, n, ib, bbase, t);               cpcommit();
    tile_load(sbase + STAGE_F * 4, x, W, n, ib + IL, bbase, t); cpcommit();

    for (int tt = 0; tt < TILES; tt++) {
        asm volatile("cp.async.wait_group 1;");
        __syncthreads();
        const int buf = tt % NSTAGE;
        const float* wsb = sm + buf * STAGE_F;
        const float* xsb = wsb + WS_F;
        const int i = ib + tt * IL + w;
        const int j = i * BATCH + bg;

        float c = __expf(g_raw[(size_t)n * BI + j]) * g_inv[j];
        ull c2 = pack2(c, c);
        ulonglong2 x01 = *(const ulonglong2*)&xsb[lane * XROW + w * 8];
        ulonglong2 x23 = *(const ulonglong2*)&xsb[lane * XROW + w * 8 + 4];
        ull xa0 = fmul2(c2, x01.x), xa1 = fmul2(c2, x01.y);
        ull xa2 = fmul2(c2, x23.x), xa3 = fmul2(c2, x23.y);
        const ulonglong2* wv = (const ulonglong2*)&wsb[w * 128];
#pragma unroll
        for (int d = 0; d < 16; d++) {
            ulonglong2 w01 = wv[2 * d], w23 = wv[2 * d + 1];
            acc[d] = ffma2(w01.x, xa0, acc[d]);
            acc[d] = ffma2(w01.y, xa1, acc[d]);
            acc[d] = ffma2(w23.x, xa2, acc[d]);
            acc[d] = ffma2(w23.y, xa3, acc[d]);
        }

        if (tt + 2 < TILES)
            tile_load(sbase + ((tt + 2) % NSTAGE) * STAGE_F * 4, x, W, n,
                      ib + (tt + 2) * IL, bbase, t);
        cpcommit();
    }

    __syncthreads();
    float* red = sm;
#pragma unroll
    for (int d = 0; d < 16; d++)
        red[w * 512 + lane * 16 + d] = hadd2(acc[d]);
    __syncthreads();
    if (t < 128) {
        int bb = t >> 2, dq = t & 3;
        float4 v = make_float4(0.f, 0.f, 0.f, 0.f);
#pragma unroll
        for (int k = 0; k < 8; k++) {
            const float* r = &red[k * 512 + bb * 16 + dq * 4];
            v.x += r[0]; v.y += r[1]; v.z += r[2]; v.w += r[3];
        }
        *(float4*)&g_part[(((size_t)s * N2 + n) * BATCH + bbase + bb) * DDIM + dq * 4] = v;
    }
}

// =====================================================================
// K4 reduce: out[b][n][d] = squash_d( sum_s part[s][n][b][d] )
// =====================================================================
__global__ void __launch_bounds__(64) cap_k4r(float* __restrict__ out) {
    const int n = blockIdx.x, b = threadIdx.x;
    float sv[16];
#pragma unroll
    for (int d = 0; d < 16; d++) sv[d] = 0.f;
    for (int sl = 0; sl < SLICES; sl++) {
        const float4* p = (const float4*)&g_part[(((size_t)sl * N2 + n) * BATCH + b) * DDIM];
#pragma unroll
        for (int q = 0; q < 4; q++) {
            float4 v = p[q];
            sv[4 * q + 0] += v.x; sv[4 * q + 1] += v.y;
            sv[4 * q + 2] += v.z; sv[4 * q + 3] += v.w;
        }
    }
    float sq = 0.f;
#pragma unroll
    for (int d = 0; d < 16; d++) sq += sv[d] * sv[d];
    float f = sq / ((1.f + sq) * sqrtf(sq + EPSF));
    float4* o = (float4*)&out[((size_t)b * N2 + n) * DDIM];
#pragma unroll
    for (int q = 0; q < 4; q++)
        o[q] = make_float4(f * sv[4 * q], f * sv[4 * q + 1],
                           f * sv[4 * q + 2], f * sv[4 * q + 3]);
}

// =====================================================================
extern "C" void kernel_launch(void* const* d_in, const int* in_sizes, int n_in,
                              void* d_out, int out_size) {
    const float* x = (const float*)d_in[0];
    const float* W = (const float*)d_in[1];
    if (n_in >= 2 && in_sizes[0] > in_sizes[1]) {
        const float* tmp = x; x = W; W = tmp;
    }
    float* out = (float*)d_out;

    dim3 g(N2, SLICES, 2);
    cap_k1p<<<g, 256>>>(x, W);
    cap_k1r<<<N2, 64>>>();
    cap_k2 <<<g, 256>>>(x, W);
    cap_k3 <<<BI / 256, 256>>>();
    cap_k4p<<<g, 256>>>(x, W);
    cap_k4r<<<N2, 64>>>(out);
}

// round 8
// speedup vs baseline: 1.1618x; 1.0370x over previous
#include <cuda_runtime.h>
#include <cstdint>

// Problem dims
#define BATCH 64
#define N1    1152
#define PDIM  8
#define N2    128
#define DDIM  16
#define KX    (N1*PDIM)          // 9216
#define BI    (BATCH*N1)         // 73728
#define EPSF  1.1920929e-7f

// tiling
#define SLICES 6
#define ISL    (N1/SLICES)       // 192 i's per slice
#define IL     8                 // i's per smem tile (= warps per block)
#define TILES  (ISL/IL)          // 24
#define XROW   68                // padded x row (word-stride ≡ 4 mod 32: conflict-free .128 phases)
#define WS_F   (IL*128)          // 1024 floats per W stage
#define XS_F   (BATCH*XROW)      // 4352 floats per x stage
#define STAGE_F (WS_F + XS_F)    // 5376 floats = 21 KB
#define NSTAGE 2                 // 42 KB static smem

typedef unsigned long long ull;

// ---------------- scratch (device globals; no allocations) ----------------
__device__ float g_raw[(size_t)N2 * N1 * BATCH];             // [n][i][b]  37.7 MB
__device__ float g_inv[BI];
__device__ float g_part[(size_t)SLICES * N2 * BATCH * DDIM]; // [s][n][b][d]

// ---------------- packed f32x2 helpers ----------------
__device__ __forceinline__ ull ffma2(ull a, ull b, ull c) {
    ull d;
    asm("fma.rn.f32x2 %0, %1, %2, %3;" : "=l"(d) : "l"(a), "l"(b), "l"(c));
    return d;
}
__device__ __forceinline__ ull fmul2(ull a, ull b) {
    ull d;
    asm("mul.rn.f32x2 %0, %1, %2;" : "=l"(d) : "l"(a), "l"(b));
    return d;
}
__device__ __forceinline__ ull pack2(float lo, float hi) {
    ull r;
    asm("mov.b64 %0, {%1, %2};" : "=l"(r) : "f"(lo), "f"(hi));
    return r;
}
__device__ __forceinline__ float hadd2(ull v) {
    float lo, hi;
    asm("mov.b64 {%0, %1}, %2;" : "=f"(lo), "=f"(hi) : "l"(v));
    return lo + hi;
}

// ---------------- cp.async helpers ----------------
__device__ __forceinline__ void cpa16(uint32_t s, const float* g) {
    asm volatile("cp.async.cg.shared.global [%0], [%1], 16;" :: "r"(s), "l"(g));
}
__device__ __forceinline__ void cpcommit() {
    asm volatile("cp.async.commit_group;");
}

// ---------------- async tile loader (5 cp.async / thread) ----------------
// stage layout: [WS_F floats W][XS_F floats x]
// W tile: [8 il][128] = W[i0+il, n, d, p] (linear d*8+p)
// x tile: [64 b][68]  = x[b, i0+il, p] at b*68 + il*8 + p
__device__ __forceinline__ void tile_load(uint32_t stage_s,
                                          const float* __restrict__ x,
                                          const float* __restrict__ W,
                                          int n, int i0, int t) {
    {   // W: 256 float4, one per thread
        int il = t >> 5, c4 = t & 31;
        cpa16(stage_s + (uint32_t)(il * 128 + c4 * 4) * 4,
              W + (size_t)(i0 + il) * (N2 * DDIM * PDIM)
                + (size_t)n * (DDIM * PDIM) + c4 * 4);
    }
    uint32_t xs_s = stage_s + WS_F * 4;
#pragma unroll
    for (int k = 0; k < 4; k++) {   // x: 1024 float4, 4 per thread
        int f4 = t + k * 256;
        int bb = f4 >> 4, r4 = f4 & 15;
        cpa16(xs_s + (uint32_t)(bb * XROW + r4 * 4) * 4,
              x + (size_t)bb * KX + i0 * PDIM + r4 * 4);
    }
}

// =====================================================================
// K1 partial: part[s][n][b][d] = sum_{i in slice, p} W[i,n,d,p] x[b,i,p]
// warp w -> il = w; lane -> b0 = lane, b1 = lane + 32
// =====================================================================
__global__ void __launch_bounds__(256, 2) cap_k1p(const float* __restrict__ x,
                                                  const float* __restrict__ W) {
    __shared__ float sm[NSTAGE * STAGE_F];
    const int n = blockIdx.x, s = blockIdx.y;
    const int t = threadIdx.x, w = t >> 5, lane = t & 31;
    const int b0 = lane, b1 = lane + 32;
    const int ib = s * ISL;
    const uint32_t sbase = (uint32_t)__cvta_generic_to_shared(sm);

    ull accA[16], accB[16];
#pragma unroll
    for (int d = 0; d < 16; d++) { accA[d] = 0ULL; accB[d] = 0ULL; }

    tile_load(sbase, x, W, n, ib, t);
    cpcommit();

    for (int tt = 0; tt < TILES; tt++) {
        asm volatile("cp.async.wait_group 0;");
        __syncthreads();
        if (tt + 1 < TILES)
            tile_load(sbase + ((tt + 1) & 1) * STAGE_F * 4, x, W, n,
                      ib + (tt + 1) * IL, t);
        cpcommit();   // uniform group count (possibly empty)

        const float* wsb = sm + (tt & 1) * STAGE_F;
        const float* xsb = wsb + WS_F;
        ulonglong2 xA01 = *(const ulonglong2*)&xsb[b0 * XROW + w * 8];
        ulonglong2 xA23 = *(const ulonglong2*)&xsb[b0 * XROW + w * 8 + 4];
        ulonglong2 xB01 = *(const ulonglong2*)&xsb[b1 * XROW + w * 8];
        ulonglong2 xB23 = *(const ulonglong2*)&xsb[b1 * XROW + w * 8 + 4];
        const ulonglong2* wv = (const ulonglong2*)&wsb[w * 128];
#pragma unroll
        for (int d = 0; d < 16; d++) {
            ulonglong2 w01 = wv[2 * d], w23 = wv[2 * d + 1];
            accA[d] = ffma2(w01.x, xA01.x, accA[d]);
            accA[d] = ffma2(w01.y, xA01.y, accA[d]);
            accA[d] = ffma2(w23.x, xA23.x, accA[d]);
            accA[d] = ffma2(w23.y, xA23.y, accA[d]);
            accB[d] = ffma2(w01.x, xB01.x, accB[d]);
            accB[d] = ffma2(w01.y, xB01.y, accB[d]);
            accB[d] = ffma2(w23.x, xB23.x, accB[d]);
            accB[d] = ffma2(w23.y, xB23.y, accB[d]);
        }
    }

    __syncthreads();
    float* red = sm;                 // [8 w][64 b][16 d] = 32 KB
#pragma unroll
    for (int d = 0; d < 16; d++) {
        red[w * 1024 + b0 * 16 + d] = hadd2(accA[d]);
        red[w * 1024 + b1 * 16 + d] = hadd2(accB[d]);
    }
    __syncthreads();
    {
        int bb = t >> 2, dq = t & 3;
        float4 v = make_float4(0.f, 0.f, 0.f, 0.f);
#pragma unroll
        for (int k = 0; k < 8; k++) {
            const float* r = &red[k * 1024 + bb * 16 + dq * 4];
            v.x += r[0]; v.y += r[1]; v.z += r[2]; v.w += r[3];
        }
        *(float4*)&g_part[(((size_t)s * N2 + n) * BATCH + bb) * DDIM + dq * 4] = v;
    }
}

// =====================================================================
// K2 (with fused K1-reduce): per-CTA recompute v0[n][b][d] from g_part,
// then raw[n][i][b] = sum_p x[b,i,p] * ( sum_d v0[n,b,d] W[i,n,d,p] )
// =====================================================================
__global__ void __launch_bounds__(256, 2) cap_k2(const float* __restrict__ x,
                                                 const float* __restrict__ W) {
    __shared__ float sm[NSTAGE * STAGE_F];
    const int n = blockIdx.x, s = blockIdx.y;
    const int t = threadIdx.x, w = t >> 5, lane = t & 31;
    const int b0 = lane, b1 = lane + 32;
    const int ib = s * ISL;
    const uint32_t sbase = (uint32_t)__cvta_generic_to_shared(sm);

    // ---- fused K1 reduce: v0 into sm[0..1023] ----
    {
        int bb = t >> 2, dq = t & 3;
        float4 v = make_float4(0.f, 0.f, 0.f, 0.f);
        for (int sl = 0; sl < SLICES; sl++) {
            float4 p = *(const float4*)&g_part[(((size_t)sl * N2 + n) * BATCH + bb) * DDIM + dq * 4];
            v.x += p.x; v.y += p.y; v.z += p.z; v.w += p.w;
        }
        *(float4*)&sm[bb * 16 + dq * 4] = v;
    }
    __syncthreads();
    if (t < 64) {
        float sv[16], sq = 0.f;
#pragma unroll
        for (int d = 0; d < 16; d++) {
            float v = sm[t * 16 + d] * (1.f / 128.f);
            sv[d] = v; sq += v * v;
        }
        float f = sq / ((1.f + sq) * sqrtf(sq + EPSF));
#pragma unroll
        for (int d = 0; d < 16; d++) sm[t * 16 + d] = f * sv[d];
    }
    __syncthreads();
    float ufA[16], ufB[16];
#pragma unroll
    for (int d = 0; d < 16; d++) {
        ufA[d] = sm[b0 * 16 + d];
        ufB[d] = sm[b1 * 16 + d];
    }
    __syncthreads();   // before tiles overwrite sm

    tile_load(sbase, x, W, n, ib, t);
    cpcommit();

    for (int tt = 0; tt < TILES; tt++) {
        asm volatile("cp.async.wait_group 0;");
        __syncthreads();
        if (tt + 1 < TILES)
            tile_load(sbase + ((tt + 1) & 1) * STAGE_F * 4, x, W, n,
                      ib + (tt + 1) * IL, t);
        cpcommit();

        const float* wsb = sm + (tt & 1) * STAGE_F;
        const float* xsb = wsb + WS_F;
        const int i = ib + tt * IL + w;
        const ulonglong2* wv = (const ulonglong2*)&wsb[w * 128];

        ull tA0 = 0, tA1 = 0, tA2 = 0, tA3 = 0;
        ull tB0 = 0, tB1 = 0, tB2 = 0, tB3 = 0;
#pragma unroll
        for (int d = 0; d < 16; d++) {
            ull uA = pack2(ufA[d], ufA[d]);
            ull uB = pack2(ufB[d], ufB[d]);
            ulonglong2 w01 = wv[2 * d], w23 = wv[2 * d + 1];
            tA0 = ffma2(uA, w01.x, tA0);
            tA1 = ffma2(uA, w01.y, tA1);
            tA2 = ffma2(uA, w23.x, tA2);
            tA3 = ffma2(uA, w23.y, tA3);
            tB0 = ffma2(uB, w01.x, tB0);
            tB1 = ffma2(uB, w01.y, tB1);
            tB2 = ffma2(uB, w23.x, tB2);
            tB3 = ffma2(uB, w23.y, tB3);
        }
        ulonglong2 xA01 = *(const ulonglong2*)&xsb[b0 * XROW + w * 8];
        ulonglong2 xA23 = *(const ulonglong2*)&xsb[b0 * XROW + w * 8 + 4];
        ulonglong2 xB01 = *(const ulonglong2*)&xsb[b1 * XROW + w * 8];
        ulonglong2 xB23 = *(const ulonglong2*)&xsb[b1 * XROW + w * 8 + 4];
        ull rA = fmul2(xA01.x, tA0);
        rA = ffma2(xA01.y, tA1, rA);
        rA = ffma2(xA23.x, tA2, rA);
        rA = ffma2(xA23.y, tA3, rA);
        ull rB = fmul2(xB01.x, tB0);
        rB = ffma2(xB01.y, tB1, rB);
        rB = ffma2(xB23.x, tB2, rB);
        rB = ffma2(xB23.y, tB3, rB);
        g_raw[(size_t)n * BI + (size_t)i * BATCH + b0] = hadd2(rA);
        g_raw[(size_t)n * BI + (size_t)i * BATCH + b1] = hadd2(rB);
    }
}

// =====================================================================
// K3: per (b,i): inv = 1 / sum_n exp(raw)  (shift-free; raw bounded,
// softmax shift-invariant)
// =====================================================================
__global__ void __launch_bounds__(256) cap_k3() {
    const int j = blockIdx.x * 256 + threadIdx.x;   // j = i*64 + b
    float s = 0.f;
#pragma unroll 16
    for (int n = 0; n < N2; n++)
        s += __expf(g_raw[(size_t)n * BI + j]);
    g_inv[j] = 1.f / s;
}

// =====================================================================
// K4 partial: part[s][n][b][d] = sum_{i in slice} c[b,i,n] * pred[b,i,n,d]
// c = exp(raw) * inv
// =====================================================================
__global__ void __launch_bounds__(256, 2) cap_k4p(const float* __restrict__ x,
                                                  const float* __restrict__ W) {
    __shared__ float sm[NSTAGE * STAGE_F];
    const int n = blockIdx.x, s = blockIdx.y;
    const int t = threadIdx.x, w = t >> 5, lane = t & 31;
    const int b0 = lane, b1 = lane + 32;
    const int ib = s * ISL;
    const uint32_t sbase = (uint32_t)__cvta_generic_to_shared(sm);

    ull accA[16], accB[16];
#pragma unroll
    for (int d = 0; d < 16; d++) { accA[d] = 0ULL; accB[d] = 0ULL; }

    tile_load(sbase, x, W, n, ib, t);
    cpcommit();

    for (int tt = 0; tt < TILES; tt++) {
        asm volatile("cp.async.wait_group 0;");
        __syncthreads();
        if (tt + 1 < TILES)
            tile_load(sbase + ((tt + 1) & 1) * STAGE_F * 4, x, W, n,
                      ib + (tt + 1) * IL, t);
        cpcommit();

        const float* wsb = sm + (tt & 1) * STAGE_F;
        const float* xsb = wsb + WS_F;
        const int i = ib + tt * IL + w;
        const int j0 = i * BATCH + b0;
        const int j1 = i * BATCH + b1;

        float cA = __expf(g_raw[(size_t)n * BI + j0]) * g_inv[j0];
        float cB = __expf(g_raw[(size_t)n * BI + j1]) * g_inv[j1];
        ull c2A = pack2(cA, cA);
        ull c2B = pack2(cB, cB);
        ulonglong2 xA01 = *(const ulonglong2*)&xsb[b0 * XROW + w * 8];
        ulonglong2 xA23 = *(const ulonglong2*)&xsb[b0 * XROW + w * 8 + 4];
        ulonglong2 xB01 = *(const ulonglong2*)&xsb[b1 * XROW + w * 8];
        ulonglong2 xB23 = *(const ulonglong2*)&xsb[b1 * XROW + w * 8 + 4];
        ull xa0 = fmul2(c2A, xA01.x), xa1 = fmul2(c2A, xA01.y);
        ull xa2 = fmul2(c2A, xA23.x), xa3 = fmul2(c2A, xA23.y);
        ull xb0 = fmul2(c2B, xB01.x), xb1 = fmul2(c2B, xB01.y);
        ull xb2 = fmul2(c2B, xB23.x), xb3 = fmul2(c2B, xB23.y);
        const ulonglong2* wv = (const ulonglong2*)&wsb[w * 128];
#pragma unroll
        for (int d = 0; d < 16; d++) {
            ulonglong2 w01 = wv[2 * d], w23 = wv[2 * d + 1];
            accA[d] = ffma2(w01.x, xa0, accA[d]);
            accA[d] = ffma2(w01.y, xa1, accA[d]);
            accA[d] = ffma2(w23.x, xa2, accA[d]);
            accA[d] = ffma2(w23.y, xa3, accA[d]);
            accB[d] = ffma2(w01.x, xb0, accB[d]);
            accB[d] = ffma2(w01.y, xb1, accB[d]);
            accB[d] = ffma2(w23.x, xb2, accB[d]);
            accB[d] = ffma2(w23.y, xb3, accB[d]);
        }
    }

    __syncthreads();
    float* red = sm;
#pragma unroll
    for (int d = 0; d < 16; d++) {
        red[w * 1024 + b0 * 16 + d] = hadd2(accA[d]);
        red[w * 1024 + b1 * 16 + d] = hadd2(accB[d]);
    }
    __syncthreads();
    {
        int bb = t >> 2, dq = t & 3;
        float4 v = make_float4(0.f, 0.f, 0.f, 0.f);
#pragma unroll
        for (int k = 0; k < 8; k++) {
            const float* r = &red[k * 1024 + bb * 16 + dq * 4];
            v.x += r[0]; v.y += r[1]; v.z += r[2]; v.w += r[3];
        }
        *(float4*)&g_part[(((size_t)s * N2 + n) * BATCH + bb) * DDIM + dq * 4] = v;
    }
}

// =====================================================================
// K4 reduce: out[b][n][d] = squash_d( sum_s part[s][n][b][d] )
// =====================================================================
__global__ void __launch_bounds__(64) cap_k4r(float* __restrict__ out) {
    const int n = blockIdx.x, b = threadIdx.x;
    float sv[16];
#pragma unroll
    for (int d = 0; d < 16; d++) sv[d] = 0.f;
    for (int sl = 0; sl < SLICES; sl++) {
        const float4* p = (const float4*)&g_part[(((size_t)sl * N2 + n) * BATCH + b) * DDIM];
#pragma unroll
        for (int q = 0; q < 4; q++) {
            float4 v = p[q];
            sv[4 * q + 0] += v.x; sv[4 * q + 1] += v.y;
            sv[4 * q + 2] += v.z; sv[4 * q + 3] += v.w;
        }
    }
    float sq = 0.f;
#pragma unroll
    for (int d = 0; d < 16; d++) sq += sv[d] * sv[d];
    float f = sq / ((1.f + sq) * sqrtf(sq + EPSF));
    float4* o = (float4*)&out[((size_t)b * N2 + n) * DDIM];
#pragma unroll
    for (int q = 0; q < 4; q++)
        o[q] = make_float4(f * sv[4 * q], f * sv[4 * q + 1],
                           f * sv[4 * q + 2], f * sv[4 * q + 3]);
}

// =====================================================================
extern "C" void kernel_launch(void* const* d_in, const int* in_sizes, int n_in,
                              void* d_out, int out_size) {
    const float* x = (const float*)d_in[0];
    const float* W = (const float*)d_in[1];
    if (n_in >= 2 && in_sizes[0] > in_sizes[1]) {
        const float* tmp = x; x = W; W = tmp;
    }
    float* out = (float*)d_out;

    dim3 g(N2, SLICES);
    cap_k1p<<<g, 256>>>(x, W);
    cap_k2 <<<g, 256>>>(x, W);
    cap_k3 <<<BI / 256, 256>>>();
    cap_k4p<<<g, 256>>>(x, W);
    cap_k4r<<<N2, 64>>>(out);
}

// round 9
// speedup vs baseline: 1.1782x; 1.0141x over previous
#include <cuda_runtime.h>
#include <cstdint>

// Problem dims
#define BATCH 64
#define N1    1152
#define PDIM  8
#define N2    128
#define DDIM  16
#define KX    (N1*PDIM)          // 9216
#define BI    (BATCH*N1)         // 73728
#define EPSF  1.1920929e-7f

// ---- slicing (shared) ----
#define SLICES 6
#define ISL    (N1/SLICES)       // 192 i's per slice

// ---- IL=8 tiling (k2) ----
#define IL8     8
#define TILES8  (ISL/IL8)        // 24
#define XROW8   68
#define WS8_F   (IL8*128)        // 1024
#define XS8_F   (BATCH*XROW8)    // 4352
#define STG8_F  (WS8_F+XS8_F)    // 5376 floats = 21 KB

// ---- IL=4 tiling (k1p/k4p, 3 CTAs/SM) ----
#define IL4     4
#define TILES4  (ISL/IL4)        // 48
#define XROW4   36               // 32 + 4 pad (word-stride ≡ 4 mod 32)
#define WS4_F   (IL4*128)        // 512
#define XS4_F   (BATCH*XROW4)    // 2304
#define STG4_F  (WS4_F+XS4_F)    // 2816 floats = 11 KB

typedef unsigned long long ull;

// ---------------- scratch (device globals; no allocations) ----------------
__device__ float g_raw[(size_t)N2 * N1 * BATCH];             // [n][i][b]  37.7 MB
__device__ float g_inv[BI];
__device__ float g_part[(size_t)SLICES * N2 * BATCH * DDIM]; // [s][n][b][d]

// ---------------- packed f32x2 helpers ----------------
__device__ __forceinline__ ull ffma2(ull a, ull b, ull c) {
    ull d;
    asm("fma.rn.f32x2 %0, %1, %2, %3;" : "=l"(d) : "l"(a), "l"(b), "l"(c));
    return d;
}
__device__ __forceinline__ ull fmul2(ull a, ull b) {
    ull d;
    asm("mul.rn.f32x2 %0, %1, %2;" : "=l"(d) : "l"(a), "l"(b));
    return d;
}
__device__ __forceinline__ ull pack2(float lo, float hi) {
    ull r;
    asm("mov.b64 %0, {%1, %2};" : "=l"(r) : "f"(lo), "f"(hi));
    return r;
}
__device__ __forceinline__ float hadd2(ull v) {
    float lo, hi;
    asm("mov.b64 {%0, %1}, %2;" : "=f"(lo), "=f"(hi) : "l"(v));
    return lo + hi;
}

// ---------------- cp.async helpers ----------------
__device__ __forceinline__ void cpa16(uint32_t s, const float* g) {
    asm volatile("cp.async.cg.shared.global [%0], [%1], 16;" :: "r"(s), "l"(g));
}
__device__ __forceinline__ void cpcommit() {
    asm volatile("cp.async.commit_group;");
}

// ---------------- IL=8 tile loader (k2) ----------------
__device__ __forceinline__ void tile_load8(uint32_t stage_s,
                                           const float* __restrict__ x,
                                           const float* __restrict__ W,
                                           int n, int i0, int t) {
    {   // W: 256 float4
        int il = t >> 5, c4 = t & 31;
        cpa16(stage_s + (uint32_t)(il * 128 + c4 * 4) * 4,
              W + (size_t)(i0 + il) * (N2 * DDIM * PDIM)
                + (size_t)n * (DDIM * PDIM) + c4 * 4);
    }
    uint32_t xs_s = stage_s + WS8_F * 4;
#pragma unroll
    for (int k = 0; k < 4; k++) {   // x: 1024 float4
        int f4 = t + k * 256;
        int bb = f4 >> 4, r4 = f4 & 15;
        cpa16(xs_s + (uint32_t)(bb * XROW8 + r4 * 4) * 4,
              x + (size_t)bb * KX + i0 * PDIM + r4 * 4);
    }
}

// ---------------- IL=4 tile loader (k1p/k4p) ----------------
__device__ __forceinline__ void tile_load4(uint32_t stage_s,
                                           const float* __restrict__ x,
                                           const float* __restrict__ W,
                                           int n, int i0, int t) {
    if (t < 128) {  // W: 128 float4
        int il = t >> 5, c4 = t & 31;
        cpa16(stage_s + (uint32_t)(il * 128 + c4 * 4) * 4,
              W + (size_t)(i0 + il) * (N2 * DDIM * PDIM)
                + (size_t)n * (DDIM * PDIM) + c4 * 4);
    }
    uint32_t xs_s = stage_s + WS4_F * 4;
#pragma unroll
    for (int k = 0; k < 2; k++) {   // x: 512 float4
        int f4 = t + k * 256;
        int bb = f4 >> 3, r4 = f4 & 7;
        cpa16(xs_s + (uint32_t)(bb * XROW4 + r4 * 4) * 4,
              x + (size_t)bb * KX + i0 * PDIM + r4 * 4);
    }
}

// =====================================================================
// K1 partial (d-split, 3 CTAs/SM):
// part[s][n][b][d] = sum_{i in slice, p} W[i,n,d,p] x[b,i,p]
// warp w: il = w&3, dh = w>>2 (d = dh*8 + j); lanes: b0=lane, b1=lane+32
// =====================================================================
__global__ void __launch_bounds__(256, 3) cap_k1p(const float* __restrict__ x,
                                                  const float* __restrict__ W) {
    __shared__ float sm[2 * STG4_F];
    const int n = blockIdx.x, s = blockIdx.y;
    const int t = threadIdx.x, w = t >> 5, lane = t & 31;
    const int il = w & 3, dh = w >> 2;
    const int b0 = lane, b1 = lane + 32;
    const int ib = s * ISL;
    const uint32_t sbase = (uint32_t)__cvta_generic_to_shared(sm);

    ull accA[8], accB[8];
#pragma unroll
    for (int j = 0; j < 8; j++) { accA[j] = 0ULL; accB[j] = 0ULL; }

    tile_load4(sbase, x, W, n, ib, t);
    cpcommit();

    for (int tt = 0; tt < TILES4; tt++) {
        asm volatile("cp.async.wait_group 0;");
        __syncthreads();
        if (tt + 1 < TILES4)
            tile_load4(sbase + ((tt + 1) & 1) * STG4_F * 4, x, W, n,
                       ib + (tt + 1) * IL4, t);
        cpcommit();   // uniform group count

        const float* wsb = sm + (tt & 1) * STG4_F;
        const float* xsb = wsb + WS4_F;
        ulonglong2 xA01 = *(const ulonglong2*)&xsb[b0 * XROW4 + il * 8];
        ulonglong2 xA23 = *(const ulonglong2*)&xsb[b0 * XROW4 + il * 8 + 4];
        ulonglong2 xB01 = *(const ulonglong2*)&xsb[b1 * XROW4 + il * 8];
        ulonglong2 xB23 = *(const ulonglong2*)&xsb[b1 * XROW4 + il * 8 + 4];
        const ulonglong2* wv = (const ulonglong2*)&wsb[il * 128 + dh * 64];
#pragma unroll
        for (int j = 0; j < 8; j++) {
            ulonglong2 w01 = wv[2 * j], w23 = wv[2 * j + 1];
            accA[j] = ffma2(w01.x, xA01.x, accA[j]);
            accA[j] = ffma2(w01.y, xA01.y, accA[j]);
            accA[j] = ffma2(w23.x, xA23.x, accA[j]);
            accA[j] = ffma2(w23.y, xA23.y, accA[j]);
            accB[j] = ffma2(w01.x, xB01.x, accB[j]);
            accB[j] = ffma2(w01.y, xB01.y, accB[j]);
            accB[j] = ffma2(w23.x, xB23.x, accB[j]);
            accB[j] = ffma2(w23.y, xB23.y, accB[j]);
        }
    }

    __syncthreads();
    float* red = sm;                 // [8 w][64 b][8 j] = 16 KB
#pragma unroll
    for (int j = 0; j < 8; j++) {
        red[w * 512 + b0 * 8 + j] = hadd2(accA[j]);
        red[w * 512 + b1 * 8 + j] = hadd2(accB[j]);
    }
    __syncthreads();
    {
        // thread t -> b = t>>2, q = t&3, d = q*4 .. q*4+3
        int bb = t >> 2, q = t & 3;
        float v[4];
#pragma unroll
        for (int e = 0; e < 4; e++) {
            int d = q * 4 + e;
            int dhh = d >> 3, j = d & 7;
            float sv = 0.f;
#pragma unroll
            for (int ill = 0; ill < 4; ill++)
                sv += red[(dhh * 4 + ill) * 512 + bb * 8 + j];
            v[e] = sv;
        }
        *(float4*)&g_part[(((size_t)s * N2 + n) * BATCH + bb) * DDIM + q * 4] =
            make_float4(v[0], v[1], v[2], v[3]);
    }
}

// =====================================================================
// K2 (with fused K1-reduce): per-CTA recompute v0 from g_part,
// then raw[n][i][b] = sum_p x[b,i,p] * ( sum_d v0[n,b,d] W[i,n,d,p] )
// =====================================================================
__global__ void __launch_bounds__(256, 2) cap_k2(const float* __restrict__ x,
                                                 const float* __restrict__ W) {
    __shared__ float sm[2 * STG8_F];
    const int n = blockIdx.x, s = blockIdx.y;
    const int t = threadIdx.x, w = t >> 5, lane = t & 31;
    const int b0 = lane, b1 = lane + 32;
    const int ib = s * ISL;
    const uint32_t sbase = (uint32_t)__cvta_generic_to_shared(sm);

    // ---- fused K1 reduce: v0 into sm[0..1023] ----
    {
        int bb = t >> 2, dq = t & 3;
        float4 v = make_float4(0.f, 0.f, 0.f, 0.f);
        for (int sl = 0; sl < SLICES; sl++) {
            float4 p = *(const float4*)&g_part[(((size_t)sl * N2 + n) * BATCH + bb) * DDIM + dq * 4];
            v.x += p.x; v.y += p.y; v.z += p.z; v.w += p.w;
        }
        *(float4*)&sm[bb * 16 + dq * 4] = v;
    }
    __syncthreads();
    if (t < 64) {
        float sv[16], sq = 0.f;
#pragma unroll
        for (int d = 0; d < 16; d++) {
            float v = sm[t * 16 + d] * (1.f / 128.f);
            sv[d] = v; sq += v * v;
        }
        float f = sq / ((1.f + sq) * sqrtf(sq + EPSF));
#pragma unroll
        for (int d = 0; d < 16; d++) sm[t * 16 + d] = f * sv[d];
    }
    __syncthreads();
    float ufA[16], ufB[16];
#pragma unroll
    for (int d = 0; d < 16; d++) {
        ufA[d] = sm[b0 * 16 + d];
        ufB[d] = sm[b1 * 16 + d];
    }
    __syncthreads();   // before tiles overwrite sm

    tile_load8(sbase, x, W, n, ib, t);
    cpcommit();

    for (int tt = 0; tt < TILES8; tt++) {
        asm volatile("cp.async.wait_group 0;");
        __syncthreads();
        if (tt + 1 < TILES8)
            tile_load8(sbase + ((tt + 1) & 1) * STG8_F * 4, x, W, n,
                       ib + (tt + 1) * IL8, t);
        cpcommit();

        const float* wsb = sm + (tt & 1) * STG8_F;
        const float* xsb = wsb + WS8_F;
        const int i = ib + tt * IL8 + w;
        const ulonglong2* wv = (const ulonglong2*)&wsb[w * 128];

        ull tA0 = 0, tA1 = 0, tA2 = 0, tA3 = 0;
        ull tB0 = 0, tB1 = 0, tB2 = 0, tB3 = 0;
#pragma unroll
        for (int d = 0; d < 16; d++) {
            ull uA = pack2(ufA[d], ufA[d]);
            ull uB = pack2(ufB[d], ufB[d]);
            ulonglong2 w01 = wv[2 * d], w23 = wv[2 * d + 1];
            tA0 = ffma2(uA, w01.x, tA0);
            tA1 = ffma2(uA, w01.y, tA1);
            tA2 = ffma2(uA, w23.x, tA2);
            tA3 = ffma2(uA, w23.y, tA3);
            tB0 = ffma2(uB, w01.x, tB0);
            tB1 = ffma2(uB, w01.y, tB1);
            tB2 = ffma2(uB, w23.x, tB2);
            tB3 = ffma2(uB, w23.y, tB3);
        }
        ulonglong2 xA01 = *(const ulonglong2*)&xsb[b0 * XROW8 + w * 8];
        ulonglong2 xA23 = *(const ulonglong2*)&xsb[b0 * XROW8 + w * 8 + 4];
        ulonglong2 xB01 = *(const ulonglong2*)&xsb[b1 * XROW8 + w * 8];
        ulonglong2 xB23 = *(const ulonglong2*)&xsb[b1 * XROW8 + w * 8 + 4];
        ull rA = fmul2(xA01.x, tA0);
        rA = ffma2(xA01.y, tA1, rA);
        rA = ffma2(xA23.x, tA2, rA);
        rA = ffma2(xA23.y, tA3, rA);
        ull rB = fmul2(xB01.x, tB0);
        rB = ffma2(xB01.y, tB1, rB);
        rB = ffma2(xB23.x, tB2, rB);
        rB = ffma2(xB23.y, tB3, rB);
        g_raw[(size_t)n * BI + (size_t)i * BATCH + b0] = hadd2(rA);
        g_raw[(size_t)n * BI + (size_t)i * BATCH + b1] = hadd2(rB);
    }
}

// =====================================================================
// K3: per (b,i): inv = 1 / sum_n exp(raw)  (shift-free; raw bounded,
// softmax shift-invariant)
// =====================================================================
__global__ void __launch_bounds__(256) cap_k3() {
    const int j = blockIdx.x * 256 + threadIdx.x;   // j = i*64 + b
    float s = 0.f;
#pragma unroll 16
    for (int n = 0; n < N2; n++)
        s += __expf(g_raw[(size_t)n * BI + j]);
    g_inv[j] = 1.f / s;
}

// =====================================================================
// K4 partial (d-split, 3 CTAs/SM):
// part[s][n][b][d] = sum_{i in slice} c[b,i,n] * pred[b,i,n,d], c=exp(raw)*inv
// =====================================================================
__global__ void __launch_bounds__(256, 3) cap_k4p(const float* __restrict__ x,
                                                  const float* __restrict__ W) {
    __shared__ float sm[2 * STG4_F];
    const int n = blockIdx.x, s = blockIdx.y;
    const int t = threadIdx.x, w = t >> 5, lane = t & 31;
    const int il = w & 3, dh = w >> 2;
    const int b0 = lane, b1 = lane + 32;
    const int ib = s * ISL;
    const uint32_t sbase = (uint32_t)__cvta_generic_to_shared(sm);

    ull accA[8], accB[8];
#pragma unroll
    for (int j = 0; j < 8; j++) { accA[j] = 0ULL; accB[j] = 0ULL; }

    tile_load4(sbase, x, W, n, ib, t);
    cpcommit();

    for (int tt = 0; tt < TILES4; tt++) {
        asm volatile("cp.async.wait_group 0;");
        __syncthreads();
        if (tt + 1 < TILES4)
            tile_load4(sbase + ((tt + 1) & 1) * STG4_F * 4, x, W, n,
                       ib + (tt + 1) * IL4, t);
        cpcommit();

        const float* wsb = sm + (tt & 1) * STG4_F;
        const float* xsb = wsb + WS4_F;
        const int i = ib + tt * IL4 + il;
        const int j0 = i * BATCH + b0;
        const int j1 = i * BATCH + b1;

        float cA = __expf(g_raw[(size_t)n * BI + j0]) * g_inv[j0];
        float cB = __expf(g_raw[(size_t)n * BI + j1]) * g_inv[j1];
        ull c2A = pack2(cA, cA);
        ull c2B = pack2(cB, cB);
        ulonglong2 xA01 = *(const ulonglong2*)&xsb[b0 * XROW4 + il * 8];
        ulonglong2 xA23 = *(const ulonglong2*)&xsb[b0 * XROW4 + il * 8 + 4];
        ulonglong2 xB01 = *(const ulonglong2*)&xsb[b1 * XROW4 + il * 8];
        ulonglong2 xB23 = *(const ulonglong2*)&xsb[b1 * XROW4 + il * 8 + 4];
        ull xa0 = fmul2(c2A, xA01.x), xa1 = fmul2(c2A, xA01.y);
        ull xa2 = fmul2(c2A, xA23.x), xa3 = fmul2(c2A, xA23.y);
        ull xb0 = fmul2(c2B, xB01.x), xb1 = fmul2(c2B, xB01.y);
        ull xb2 = fmul2(c2B, xB23.x), xb3 = fmul2(c2B, xB23.y);
        const ulonglong2* wv = (const ulonglong2*)&wsb[il * 128 + dh * 64];
#pragma unroll
        for (int j = 0; j < 8; j++) {
            ulonglong2 w01 = wv[2 * j], w23 = wv[2 * j + 1];
            accA[j] = ffma2(w01.x, xa0, accA[j]);
            accA[j] = ffma2(w01.y, xa1, accA[j]);
            accA[j] = ffma2(w23.x, xa2, accA[j]);
            accA[j] = ffma2(w23.y, xa3, accA[j]);
            accB[j] = ffma2(w01.x, xb0, accB[j]);
            accB[j] = ffma2(w01.y, xb1, accB[j]);
            accB[j] = ffma2(w23.x, xb2, accB[j]);
            accB[j] = ffma2(w23.y, xb3, accB[j]);
        }
    }

    __syncthreads();
    float* red = sm;                 // [8 w][64 b][8 j] = 16 KB
#pragma unroll
    for (int j = 0; j < 8; j++) {
        red[w * 512 + b0 * 8 + j] = hadd2(accA[j]);
        red[w * 512 + b1 * 8 + j] = hadd2(accB[j]);
    }
    __syncthreads();
    {
        int bb = t >> 2, q = t & 3;
        float v[4];
#pragma unroll
        for (int e = 0; e < 4; e++) {
            int d = q * 4 + e;
            int dhh = d >> 3, j = d & 7;
            float sv = 0.f;
#pragma unroll
            for (int ill = 0; ill < 4; ill++)
                sv += red[(dhh * 4 + ill) * 512 + bb * 8 + j];
            v[e] = sv;
        }
        *(float4*)&g_part[(((size_t)s * N2 + n) * BATCH + bb) * DDIM + q * 4] =
            make_float4(v[0], v[1], v[2], v[3]);
    }
}

// =====================================================================
// K4 reduce: out[b][n][d] = squash_d( sum_s part[s][n][b][d] )
// =====================================================================
__global__ void __launch_bounds__(64) cap_k4r(float* __restrict__ out) {
    const int n = blockIdx.x, b = threadIdx.x;
    float sv[16];
#pragma unroll
    for (int d = 0; d < 16; d++) sv[d] = 0.f;
    for (int sl = 0; sl < SLICES; sl++) {
        const float4* p = (const float4*)&g_part[(((size_t)sl * N2 + n) * BATCH + b) * DDIM];
#pragma unroll
        for (int q = 0; q < 4; q++) {
            float4 v = p[q];
            sv[4 * q + 0] += v.x; sv[4 * q + 1] += v.y;
            sv[4 * q + 2] += v.z; sv[4 * q + 3] += v.w;
        }
    }
    float sq = 0.f;
#pragma unroll
    for (int d = 0; d < 16; d++) sq += sv[d] * sv[d];
    float f = sq / ((1.f + sq) * sqrtf(sq + EPSF));
    float4* o = (float4*)&out[((size_t)b * N2 + n) * DDIM];
#pragma unroll
    for (int q = 0; q < 4; q++)
        o[q] = make_float4(f * sv[4 * q], f * sv[4 * q + 1],
                           f * sv[4 * q + 2], f * sv[4 * q + 3]);
}

// =====================================================================
extern "C" void kernel_launch(void* const* d_in, const int* in_sizes, int n_in,
                              void* d_out, int out_size) {
    const float* x = (const float*)d_in[0];
    const float* W = (const float*)d_in[1];
    if (n_in >= 2 && in_sizes[0] > in_sizes[1]) {
        const float* tmp = x; x = W; W = tmp;
    }
    float* out = (float*)d_out;

    dim3 g(N2, SLICES);
    cap_k1p<<<g, 256>>>(x, W);
    cap_k2 <<<g, 256>>>(x, W);
    cap_k3 <<<BI / 256, 256>>>();
    cap_k4p<<<g, 256>>>(x, W);
    cap_k4r<<<N2, 64>>>(out);
}

// round 10
// speedup vs baseline: 1.3208x; 1.1210x over previous
#include <cuda_runtime.h>
#include <cstdint>

// Problem dims
#define BATCH 64
#define N1    1152
#define PDIM  8
#define N2    128
#define DDIM  16
#define KX    (N1*PDIM)          // 9216
#define BI    (BATCH*N1)         // 73728
#define EPSF  1.1920929e-7f

// ---- tiling ----
#define SLICES 9
#define ISL    (N1/SLICES)       // 128 i's per slice
#define IL     8                 // i's per smem tile
#define TILES  (ISL/IL)          // 16
#define NW     4                 // n's per CTA
#define NBLK   (N2/NW)           // 32
#define XROW   68                // padded x row
#define WS_F   (NW*IL*128)       // 4096 floats
#define XS_F   (BATCH*XROW)      // 4352 floats
#define STAGE_F (WS_F+XS_F)      // 8448 floats = 33 KB
#define SM_MAIN (2*STAGE_F*4)    // 67584 B
#define V0_F   (NW*DDIM*BATCH)   // 4096 floats
#define SM_K2  (SM_MAIN + V0_F*4) // 83968 B

typedef unsigned long long ull;

// ---------------- scratch (device globals; no allocations) ----------------
__device__ float g_raw[(size_t)N2 * N1 * BATCH];             // [n][i][b]  37.7 MB
__device__ float g_inv[BI];
__device__ float g_part[(size_t)SLICES * N2 * BATCH * DDIM]; // [s][n][b][d]

// ---------------- packed f32x2 helpers ----------------
__device__ __forceinline__ ull ffma2(ull a, ull b, ull c) {
    ull d;
    asm("fma.rn.f32x2 %0, %1, %2, %3;" : "=l"(d) : "l"(a), "l"(b), "l"(c));
    return d;
}
__device__ __forceinline__ ull fmul2(ull a, ull b) {
    ull d;
    asm("mul.rn.f32x2 %0, %1, %2;" : "=l"(d) : "l"(a), "l"(b));
    return d;
}
__device__ __forceinline__ ull pack2(float lo, float hi) {
    ull r;
    asm("mov.b64 %0, {%1, %2};" : "=l"(r) : "f"(lo), "f"(hi));
    return r;
}
__device__ __forceinline__ float hadd2(ull v) {
    float lo, hi;
    asm("mov.b64 {%0, %1}, %2;" : "=f"(lo), "=f"(hi) : "l"(v));
    return lo + hi;
}

// ---------------- cp.async helpers ----------------
__device__ __forceinline__ void cpa16(uint32_t s, const float* g) {
    asm volatile("cp.async.cg.shared.global [%0], [%1], 16;" :: "r"(s), "l"(g));
}
__device__ __forceinline__ void cpcommit() {
    asm volatile("cp.async.commit_group;");
}

// ---------------- tile loader: 8 cp.async / thread ----------------
// stage: [NW nn][IL il][128] W floats, then [64 b][XROW] x floats
__device__ __forceinline__ void tile_load(uint32_t stage_s,
                                          const float* __restrict__ x,
                                          const float* __restrict__ W,
                                          int n0, int i0, int t) {
    int il = t >> 5, c4 = t & 31;
#pragma unroll
    for (int nn = 0; nn < NW; nn++) {
        cpa16(stage_s + (uint32_t)((nn * IL + il) * 128 + c4 * 4) * 4,
              W + (size_t)(i0 + il) * (N2 * DDIM * PDIM)
                + (size_t)(n0 + nn) * (DDIM * PDIM) + c4 * 4);
    }
    uint32_t xs_s = stage_s + WS_F * 4;
#pragma unroll
    for (int k = 0; k < 4; k++) {
        int f4 = t + k * 256;
        int bb = f4 >> 4, r4 = f4 & 15;
        cpa16(xs_s + (uint32_t)(bb * XROW + r4 * 4) * 4,
              x + (size_t)bb * KX + i0 * PDIM + r4 * 4);
    }
}

// =====================================================================
// K1 partial: part[s][n0+nn][b][d] = sum_{i in slice, p} W[i,n,d,p] x[b,i,p]
// warp w: dq = w&3 (d = dq*4+e), ilh = w>>2 (il = ilh*4+ii); b0=lane,b1=lane+32
// =====================================================================
__global__ void __launch_bounds__(256, 2) cap_k1p(const float* __restrict__ x,
                                                  const float* __restrict__ W) {
    extern __shared__ float sm[];
    const int n0 = blockIdx.x * NW, s = blockIdx.y;
    const int t = threadIdx.x, w = t >> 5, lane = t & 31;
    const int dq = w & 3, ilh = w >> 2;
    const int b0 = lane, b1 = lane + 32;
    const int ib = s * ISL;
    const uint32_t sbase = (uint32_t)__cvta_generic_to_shared(sm);

    ull accA[NW][4], accB[NW][4];
#pragma unroll
    for (int nn = 0; nn < NW; nn++)
#pragma unroll
        for (int e = 0; e < 4; e++) { accA[nn][e] = 0ULL; accB[nn][e] = 0ULL; }

    tile_load(sbase, x, W, n0, ib, t);
    cpcommit();

    for (int tt = 0; tt < TILES; tt++) {
        asm volatile("cp.async.wait_group 0;");
        __syncthreads();
        if (tt + 1 < TILES)
            tile_load(sbase + ((tt + 1) & 1) * STAGE_F * 4, x, W, n0,
                      ib + (tt + 1) * IL, t);
        cpcommit();

        const float* wsb = sm + (tt & 1) * STAGE_F;
        const float* xsb = wsb + WS_F;
#pragma unroll
        for (int ii = 0; ii < 4; ii++) {
            const int il = ilh * 4 + ii;
            ulonglong2 xA01 = *(const ulonglong2*)&xsb[b0 * XROW + il * 8];
            ulonglong2 xA23 = *(const ulonglong2*)&xsb[b0 * XROW + il * 8 + 4];
            ulonglong2 xB01 = *(const ulonglong2*)&xsb[b1 * XROW + il * 8];
            ulonglong2 xB23 = *(const ulonglong2*)&xsb[b1 * XROW + il * 8 + 4];
#pragma unroll
            for (int nn = 0; nn < NW; nn++) {
                const ulonglong2* wv =
                    (const ulonglong2*)&wsb[(nn * IL + il) * 128 + dq * 32];
#pragma unroll
                for (int e = 0; e < 4; e++) {
                    ulonglong2 w01 = wv[2 * e], w23 = wv[2 * e + 1];
                    accA[nn][e] = ffma2(w01.x, xA01.x, accA[nn][e]);
                    accA[nn][e] = ffma2(w01.y, xA01.y, accA[nn][e]);
                    accA[nn][e] = ffma2(w23.x, xA23.x, accA[nn][e]);
                    accA[nn][e] = ffma2(w23.y, xA23.y, accA[nn][e]);
                    accB[nn][e] = ffma2(w01.x, xB01.x, accB[nn][e]);
                    accB[nn][e] = ffma2(w01.y, xB01.y, accB[nn][e]);
                    accB[nn][e] = ffma2(w23.x, xB23.x, accB[nn][e]);
                    accB[nn][e] = ffma2(w23.y, xB23.y, accB[nn][e]);
                }
            }
        }
    }

    __syncthreads();
    float* red = sm;     // [8 w][64 b][16 nn*4+e] = 8192 f
#pragma unroll
    for (int nn = 0; nn < NW; nn++)
#pragma unroll
        for (int e = 0; e < 4; e++) {
            red[w * 1024 + b0 * 16 + nn * 4 + e] = hadd2(accA[nn][e]);
            red[w * 1024 + b1 * 16 + nn * 4 + e] = hadd2(accB[nn][e]);
        }
    __syncthreads();
    {
        int bb = t >> 2, q = t & 3;
#pragma unroll
        for (int nn = 0; nn < NW; nn++) {
            float v[4];
#pragma unroll
            for (int e = 0; e < 4; e++)
                v[e] = red[(0 * 4 + q) * 1024 + bb * 16 + nn * 4 + e]
                     + red[(1 * 4 + q) * 1024 + bb * 16 + nn * 4 + e];
            *(float4*)&g_part[(((size_t)s * N2 + n0 + nn) * BATCH + bb) * DDIM + q * 4] =
                make_float4(v[0], v[1], v[2], v[3]);
        }
    }
}

// =====================================================================
// K2 (fused K1-reduce): v0 for 4 n's into smem [nn][d][b], then
// raw[n][i][b] = sum_p x[b,i,p] * ( sum_d v0[n,b,d] W[i,n,d,p] )
// warp w -> il = w
// =====================================================================
__global__ void __launch_bounds__(256, 2) cap_k2(const float* __restrict__ x,
                                                 const float* __restrict__ W) {
    extern __shared__ float sm[];
    float* v0s = sm + 2 * STAGE_F;       // [nn][d][b] 4096 f
    const int n0 = blockIdx.x * NW, s = blockIdx.y;
    const int t = threadIdx.x, w = t >> 5, lane = t & 31;
    const int b0 = lane, b1 = lane + 32;
    const int ib = s * ISL;
    const uint32_t sbase = (uint32_t)__cvta_generic_to_shared(sm);

    // ---- fused K1 reduce into sm temp [nn][b][d] ----
    {
        int bb = t >> 2, q = t & 3;
#pragma unroll
        for (int nn = 0; nn < NW; nn++) {
            float4 v = make_float4(0.f, 0.f, 0.f, 0.f);
            for (int sl = 0; sl < SLICES; sl++) {
                float4 p = *(const float4*)&g_part[(((size_t)sl * N2 + n0 + nn) * BATCH + bb) * DDIM + q * 4];
                v.x += p.x; v.y += p.y; v.z += p.z; v.w += p.w;
            }
            *(float4*)&sm[(nn * BATCH + bb) * DDIM + q * 4] = v;
        }
    }
    __syncthreads();
    {   // squash + transpose: t -> nn = t>>6, b = t&63
        int nn = t >> 6, b = t & 63;
        float sv[16], sq = 0.f;
#pragma unroll
        for (int d = 0; d < 16; d++) {
            float v = sm[(nn * BATCH + b) * DDIM + d] * (1.f / 128.f);
            sv[d] = v; sq += v * v;
        }
        float f = sq / ((1.f + sq) * sqrtf(sq + EPSF));
        __syncthreads();   // all reads of temp done before overwrite below? (v0s is separate; sync for tile reuse of sm)
#pragma unroll
        for (int d = 0; d < 16; d++)
            v0s[(nn * DDIM + d) * BATCH + b] = f * sv[d];
    }
    __syncthreads();

    tile_load(sbase, x, W, n0, ib, t);
    cpcommit();

    for (int tt = 0; tt < TILES; tt++) {
        asm volatile("cp.async.wait_group 0;");
        __syncthreads();
        if (tt + 1 < TILES)
            tile_load(sbase + ((tt + 1) & 1) * STAGE_F * 4, x, W, n0,
                      ib + (tt + 1) * IL, t);
        cpcommit();

        const float* wsb = sm + (tt & 1) * STAGE_F;
        const float* xsb = wsb + WS_F;
        const int i = ib + tt * IL + w;
        ulonglong2 xA01 = *(const ulonglong2*)&xsb[b0 * XROW + w * 8];
        ulonglong2 xA23 = *(const ulonglong2*)&xsb[b0 * XROW + w * 8 + 4];
        ulonglong2 xB01 = *(const ulonglong2*)&xsb[b1 * XROW + w * 8];
        ulonglong2 xB23 = *(const ulonglong2*)&xsb[b1 * XROW + w * 8 + 4];

#pragma unroll
        for (int nn = 0; nn < NW; nn++) {
            const ulonglong2* wv = (const ulonglong2*)&wsb[(nn * IL + w) * 128];
            ull tA0 = 0, tA1 = 0, tA2 = 0, tA3 = 0;
            ull tB0 = 0, tB1 = 0, tB2 = 0, tB3 = 0;
#pragma unroll
            for (int d = 0; d < 16; d++) {
                float uA = v0s[(nn * DDIM + d) * BATCH + b0];
                float uB = v0s[(nn * DDIM + d) * BATCH + b1];
                ull u2A = pack2(uA, uA);
                ull u2B = pack2(uB, uB);
                ulonglong2 w01 = wv[2 * d], w23 = wv[2 * d + 1];
                tA0 = ffma2(u2A, w01.x, tA0);
                tA1 = ffma2(u2A, w01.y, tA1);
                tA2 = ffma2(u2A, w23.x, tA2);
                tA3 = ffma2(u2A, w23.y, tA3);
                tB0 = ffma2(u2B, w01.x, tB0);
                tB1 = ffma2(u2B, w01.y, tB1);
                tB2 = ffma2(u2B, w23.x, tB2);
                tB3 = ffma2(u2B, w23.y, tB3);
            }
            ull rA = fmul2(xA01.x, tA0);
            rA = ffma2(xA01.y, tA1, rA);
            rA = ffma2(xA23.x, tA2, rA);
            rA = ffma2(xA23.y, tA3, rA);
            ull rB = fmul2(xB01.x, tB0);
            rB = ffma2(xB01.y, tB1, rB);
            rB = ffma2(xB23.x, tB2, rB);
            rB = ffma2(xB23.y, tB3, rB);
            g_raw[(size_t)(n0 + nn) * BI + (size_t)i * BATCH + b0] = hadd2(rA);
            g_raw[(size_t)(n0 + nn) * BI + (size_t)i * BATCH + b1] = hadd2(rB);
        }
    }
}

// =====================================================================
// K3: per (b,i): inv = 1 / sum_n exp(raw)  (shift-free; raw bounded,
// softmax shift-invariant)
// =====================================================================
__global__ void __launch_bounds__(256) cap_k3() {
    const int j = blockIdx.x * 256 + threadIdx.x;   // j = i*64 + b
    float s0 = 0.f, s1 = 0.f;
#pragma unroll 8
    for (int n = 0; n < N2; n += 2) {
        s0 += __expf(g_raw[(size_t)n * BI + j]);
        s1 += __expf(g_raw[(size_t)(n + 1) * BI + j]);
    }
    g_inv[j] = 1.f / (s0 + s1);
}

// =====================================================================
// K4 partial: part[s][n0+nn][b][d] = sum_{i in slice} c * pred,
// c = exp(raw[n,i,b]) * inv[i,b]
// =====================================================================
__global__ void __launch_bounds__(256, 2) cap_k4p(const float* __restrict__ x,
                                                  const float* __restrict__ W) {
    extern __shared__ float sm[];
    const int n0 = blockIdx.x * NW, s = blockIdx.y;
    const int t = threadIdx.x, w = t >> 5, lane = t & 31;
    const int dq = w & 3, ilh = w >> 2;
    const int b0 = lane, b1 = lane + 32;
    const int ib = s * ISL;
    const uint32_t sbase = (uint32_t)__cvta_generic_to_shared(sm);

    ull accA[NW][4], accB[NW][4];
#pragma unroll
    for (int nn = 0; nn < NW; nn++)
#pragma unroll
        for (int e = 0; e < 4; e++) { accA[nn][e] = 0ULL; accB[nn][e] = 0ULL; }

    tile_load(sbase, x, W, n0, ib, t);
    cpcommit();

    for (int tt = 0; tt < TILES; tt++) {
        asm volatile("cp.async.wait_group 0;");
        __syncthreads();
        if (tt + 1 < TILES)
            tile_load(sbase + ((tt + 1) & 1) * STAGE_F * 4, x, W, n0,
                      ib + (tt + 1) * IL, t);
        cpcommit();

        const float* wsb = sm + (tt & 1) * STAGE_F;
        const float* xsb = wsb + WS_F;
#pragma unroll
        for (int ii = 0; ii < 4; ii++) {
            const int il = ilh * 4 + ii;
            const int i = ib + tt * IL + il;
            const float invA = g_inv[i * BATCH + b0];
            const float invB = g_inv[i * BATCH + b1];
            ulonglong2 xA01 = *(const ulonglong2*)&xsb[b0 * XROW + il * 8];
            ulonglong2 xA23 = *(const ulonglong2*)&xsb[b0 * XROW + il * 8 + 4];
            ulonglong2 xB01 = *(const ulonglong2*)&xsb[b1 * XROW + il * 8];
            ulonglong2 xB23 = *(const ulonglong2*)&xsb[b1 * XROW + il * 8 + 4];
#pragma unroll
            for (int nn = 0; nn < NW; nn++) {
                float cA = __expf(g_raw[(size_t)(n0 + nn) * BI + (size_t)i * BATCH + b0]) * invA;
                float cB = __expf(g_raw[(size_t)(n0 + nn) * BI + (size_t)i * BATCH + b1]) * invB;
                ull c2A = pack2(cA, cA);
                ull c2B = pack2(cB, cB);
                ull xa0 = fmul2(c2A, xA01.x), xa1 = fmul2(c2A, xA01.y);
                ull xa2 = fmul2(c2A, xA23.x), xa3 = fmul2(c2A, xA23.y);
                ull xb0 = fmul2(c2B, xB01.x), xb1 = fmul2(c2B, xB01.y);
                ull xb2 = fmul2(c2B, xB23.x), xb3 = fmul2(c2B, xB23.y);
                const ulonglong2* wv =
                    (const ulonglong2*)&wsb[(nn * IL + il) * 128 + dq * 32];
#pragma unroll
                for (int e = 0; e < 4; e++) {
                    ulonglong2 w01 = wv[2 * e], w23 = wv[2 * e + 1];
                    accA[nn][e] = ffma2(w01.x, xa0, accA[nn][e]);
                    accA[nn][e] = ffma2(w01.y, xa1, accA[nn][e]);
                    accA[nn][e] = ffma2(w23.x, xa2, accA[nn][e]);
                    accA[nn][e] = ffma2(w23.y, xa3, accA[nn][e]);
                    accB[nn][e] = ffma2(w01.x, xb0, accB[nn][e]);
                    accB[nn][e] = ffma2(w01.y, xb1, accB[nn][e]);
                    accB[nn][e] = ffma2(w23.x, xb2, accB[nn][e]);
                    accB[nn][e] = ffma2(w23.y, xb3, accB[nn][e]);
                }
            }
        }
    }

    __syncthreads();
    float* red = sm;
#pragma unroll
    for (int nn = 0; nn < NW; nn++)
#pragma unroll
        for (int e = 0; e < 4; e++) {
            red[w * 1024 + b0 * 16 + nn * 4 + e] = hadd2(accA[nn][e]);
            red[w * 1024 + b1 * 16 + nn * 4 + e] = hadd2(accB[nn][e]);
        }
    __syncthreads();
    {
        int bb = t >> 2, q = t & 3;
#pragma unroll
        for (int nn = 0; nn < NW; nn++) {
            float v[4];
#pragma unroll
            for (int e = 0; e < 4; e++)
                v[e] = red[(0 * 4 + q) * 1024 + bb * 16 + nn * 4 + e]
                     + red[(1 * 4 + q) * 1024 + bb * 16 + nn * 4 + e];
            *(float4*)&g_part[(((size_t)s * N2 + n0 + nn) * BATCH + bb) * DDIM + q * 4] =
                make_float4(v[0], v[1], v[2], v[3]);
        }
    }
}

// =====================================================================
// K4 reduce: out[b][n][d] = squash_d( sum_s part[s][n][b][d] )
// =====================================================================
__global__ void __launch_bounds__(64) cap_k4r(float* __restrict__ out) {
    const int n = blockIdx.x, b = threadIdx.x;
    float sv[16];
#pragma unroll
    for (int d = 0; d < 16; d++) sv[d] = 0.f;
    for (int sl = 0; sl < SLICES; sl++) {
        const float4* p = (const float4*)&g_part[(((size_t)sl * N2 + n) * BATCH + b) * DDIM];
#pragma unroll
        for (int q = 0; q < 4; q++) {
            float4 v = p[q];
            sv[4 * q + 0] += v.x; sv[4 * q + 1] += v.y;
            sv[4 * q + 2] += v.z; sv[4 * q + 3] += v.w;
        }
    }
    float sq = 0.f;
#pragma unroll
    for (int d = 0; d < 16; d++) sq += sv[d] * sv[d];
    float f = sq / ((1.f + sq) * sqrtf(sq + EPSF));
    float4* o = (float4*)&out[((size_t)b * N2 + n) * DDIM];
#pragma unroll
    for (int q = 0; q < 4; q++)
        o[q] = make_float4(f * sv[4 * q], f * sv[4 * q + 1],
                           f * sv[4 * q + 2], f * sv[4 * q + 3]);
}

// =====================================================================
extern "C" void kernel_launch(void* const* d_in, const int* in_sizes, int n_in,
                              void* d_out, int out_size) {
    const float* x = (const float*)d_in[0];
    const float* W = (const float*)d_in[1];
    if (n_in >= 2 && in_sizes[0] > in_sizes[1]) {
        const float* tmp = x; x = W; W = tmp;
    }
    float* out = (float*)d_out;

    cudaFuncSetAttribute(cap_k1p, cudaFuncAttributeMaxDynamicSharedMemorySize, SM_MAIN);
    cudaFuncSetAttribute(cap_k2,  cudaFuncAttributeMaxDynamicSharedMemorySize, SM_K2);
    cudaFuncSetAttribute(cap_k4p, cudaFuncAttributeMaxDynamicSharedMemorySize, SM_MAIN);

    dim3 g(NBLK, SLICES);
    cap_k1p<<<g, 256, SM_MAIN>>>(x, W);
    cap_k2 <<<g, 256, SM_K2 >>>(x, W);
    cap_k3 <<<BI / 256, 256>>>();
    cap_k4p<<<g, 256, SM_MAIN>>>(x, W);
    cap_k4r<<<N2, 64>>>(out);
}

// round 12
// speedup vs baseline: 1.3982x; 1.0586x over previous
#include <cuda_runtime.h>
#include <cstdint>

// Problem dims
#define BATCH 64
#define N1    1152
#define PDIM  8
#define N2    128
#define DDIM  16
#define KX    (N1*PDIM)          // 9216
#define BI    (BATCH*N1)         // 73728
#define EPSF  1.1920929e-7f

// ---- tiling ----
#define SLICES 9
#define ISL    (N1/SLICES)       // 128 i's per slice
#define IL     8                 // i's per smem tile
#define TILES  (ISL/IL)          // 16
#define NW     4                 // n's per CTA
#define NBLK   (N2/NW)           // 32
#define XROW   68                // padded x row (conflict-free phases)
#define WS_F   (NW*IL*128)       // 4096 floats  (layout [il][nn][128])
#define XS_F   (BATCH*XROW)      // 4352 floats
#define STAGE_F (WS_F+XS_F)      // 8448 floats = 33 KB
#define SM_MAIN (2*STAGE_F*4)    // 67584 B
#define V0_F   (NW*DDIM*BATCH)   // 4096 floats
#define SM_K2  (SM_MAIN + V0_F*4) // 83968 B
#define STAGE_BYTES 32768u       // 16 KB W + 16 KB x payload per stage
#define LANE_BYTES  4096u        // per producer lane (8 lanes)

typedef unsigned long long ull;

// ---------------- scratch (device globals; no allocations) ----------------
__device__ float g_raw[(size_t)N2 * N1 * BATCH];             // [n][i][b]; k3 converts to c in-place
__device__ float g_part[(size_t)SLICES * N2 * BATCH * DDIM]; // [s][n][b][d]

// ---------------- packed f32x2 helpers ----------------
__device__ __forceinline__ ull ffma2(ull a, ull b, ull c) {
    ull d;
    asm("fma.rn.f32x2 %0, %1, %2, %3;" : "=l"(d) : "l"(a), "l"(b), "l"(c));
    return d;
}
__device__ __forceinline__ ull fmul2(ull a, ull b) {
    ull d;
    asm("mul.rn.f32x2 %0, %1, %2;" : "=l"(d) : "l"(a), "l"(b));
    return d;
}
__device__ __forceinline__ ull pack2(float lo, float hi) {
    ull r;
    asm("mov.b64 %0, {%1, %2};" : "=l"(r) : "f"(lo), "f"(hi));
    return r;
}
__device__ __forceinline__ float hadd2(ull v) {
    float lo, hi;
    asm("mov.b64 {%0, %1}, %2;" : "=f"(lo), "=f"(hi) : "l"(v));
    return lo + hi;
}

// ---------------- bulk-async (TMA) + mbarrier helpers ----------------
__device__ __forceinline__ void mbar_init(uint32_t mbar, uint32_t count) {
    asm volatile("mbarrier.init.shared.b64 [%0], %1;" :: "r"(mbar), "r"(count) : "memory");
}
__device__ __forceinline__ void mbar_arrive_tx(uint32_t mbar, uint32_t bytes) {
    asm volatile("mbarrier.arrive.expect_tx.shared.b64 _, [%0], %1;"
                 :: "r"(mbar), "r"(bytes) : "memory");
}
__device__ __forceinline__ void mbar_wait(uint32_t mbar, uint32_t parity) {
    asm volatile(
        "{\n\t.reg .pred P;\n\t"
        "WL_%=:\n\t"
        "mbarrier.try_wait.parity.shared.b64 P, [%0], %1;\n\t"
        "@!P bra WL_%=;\n\t}"
        :: "r"(mbar), "r"(parity) : "memory");
}
__device__ __forceinline__ void cpbulk(uint32_t dst, const float* src,
                                       uint32_t bytes, uint32_t mbar) {
    asm volatile(
        "cp.async.bulk.shared::cta.global.mbarrier::complete_tx::bytes [%0], [%1], %2, [%3];"
        :: "r"(dst), "l"(src), "r"(bytes), "r"(mbar) : "memory");
}

// ---------------- bulk tile loader: 72 copies, 8 producer lanes ----------
// stage: [IL il][NW nn][128] W floats, then [64 b][XROW] x floats
__device__ __forceinline__ void tile_load(uint32_t stage_s, uint32_t mbar,
                                          const float* __restrict__ x,
                                          const float* __restrict__ W,
                                          int n0, int i0, int t) {
    if (t < 8) {
        mbar_arrive_tx(mbar, LANE_BYTES);
        const int il = t;
        // W: 4 consecutive n rows for this il = 2048 contiguous bytes
        cpbulk(stage_s + (uint32_t)(il * NW * 128) * 4,
               W + (size_t)(i0 + il) * (N2 * DDIM * PDIM)
                 + (size_t)n0 * (DDIM * PDIM),
               2048, mbar);
        // x: rows b = il*8 .. il*8+7, 256 contiguous bytes each
        uint32_t xs_s = stage_s + WS_F * 4;
#pragma unroll
        for (int r = 0; r < 8; r++) {
            const int b = il * 8 + r;
            cpbulk(xs_s + (uint32_t)(b * XROW) * 4,
                   x + (size_t)b * KX + i0 * PDIM, 256, mbar);
        }
    }
}

// =====================================================================
// K1 partial: part[s][n0+nn][b][d] = sum_{i in slice, p} W[i,n,d,p] x[b,i,p]
// warp w: dq = w&3 (d = dq*4+e), ilh = w>>2 (il = ilh*4+ii); b0=lane,b1=lane+32
// =====================================================================
__global__ void __launch_bounds__(256, 2) cap_k1p(const float* __restrict__ x,
                                                  const float* __restrict__ W) {
    extern __shared__ float sm[];
    __shared__ __align__(8) ull mbars[2];
    const int n0 = blockIdx.x * NW, s = blockIdx.y;
    const int t = threadIdx.x, w = t >> 5, lane = t & 31;
    const int dq = w & 3, ilh = w >> 2;
    const int b0 = lane, b1 = lane + 32;
    const int ib = s * ISL;
    const uint32_t sbase = (uint32_t)__cvta_generic_to_shared(sm);
    const uint32_t mb[2] = { (uint32_t)__cvta_generic_to_shared(&mbars[0]),
                             (uint32_t)__cvta_generic_to_shared(&mbars[1]) };

    if (t == 0) { mbar_init(mb[0], 8); mbar_init(mb[1], 8); }
    __syncthreads();

    ull accA[NW][4], accB[NW][4];
#pragma unroll
    for (int nn = 0; nn < NW; nn++)
#pragma unroll
        for (int e = 0; e < 4; e++) { accA[nn][e] = 0ULL; accB[nn][e] = 0ULL; }

    tile_load(sbase, mb[0], x, W, n0, ib, t);

    for (int tt = 0; tt < TILES; tt++) {
        mbar_wait(mb[tt & 1], (tt >> 1) & 1);
        __syncthreads();
        if (tt + 1 < TILES)
            tile_load(sbase + ((tt + 1) & 1) * STAGE_F * 4, mb[(tt + 1) & 1],
                      x, W, n0, ib + (tt + 1) * IL, t);

        const float* wsb = sm + (tt & 1) * STAGE_F;
        const float* xsb = wsb + WS_F;
#pragma unroll
        for (int ii = 0; ii < 4; ii++) {
            const int il = ilh * 4 + ii;
            ulonglong2 xA01 = *(const ulonglong2*)&xsb[b0 * XROW + il * 8];
            ulonglong2 xA23 = *(const ulonglong2*)&xsb[b0 * XROW + il * 8 + 4];
            ulonglong2 xB01 = *(const ulonglong2*)&xsb[b1 * XROW + il * 8];
            ulonglong2 xB23 = *(const ulonglong2*)&xsb[b1 * XROW + il * 8 + 4];
#pragma unroll
            for (int nn = 0; nn < NW; nn++) {
                const ulonglong2* wv =
                    (const ulonglong2*)&wsb[(il * NW + nn) * 128 + dq * 32];
#pragma unroll
                for (int e = 0; e < 4; e++) {
                    ulonglong2 w01 = wv[2 * e], w23 = wv[2 * e + 1];
                    accA[nn][e] = ffma2(w01.x, xA01.x, accA[nn][e]);
                    accA[nn][e] = ffma2(w01.y, xA01.y, accA[nn][e]);
                    accA[nn][e] = ffma2(w23.x, xA23.x, accA[nn][e]);
                    accA[nn][e] = ffma2(w23.y, xA23.y, accA[nn][e]);
                    accB[nn][e] = ffma2(w01.x, xB01.x, accB[nn][e]);
                    accB[nn][e] = ffma2(w01.y, xB01.y, accB[nn][e]);
                    accB[nn][e] = ffma2(w23.x, xB23.x, accB[nn][e]);
                    accB[nn][e] = ffma2(w23.y, xB23.y, accB[nn][e]);
                }
            }
        }
    }

    __syncthreads();
    float* red = sm;     // [8 w][64 b][16 nn*4+e] = 8192 f
#pragma unroll
    for (int nn = 0; nn < NW; nn++)
#pragma unroll
        for (int e = 0; e < 4; e++) {
            red[w * 1024 + b0 * 16 + nn * 4 + e] = hadd2(accA[nn][e]);
            red[w * 1024 + b1 * 16 + nn * 4 + e] = hadd2(accB[nn][e]);
        }
    __syncthreads();
    {
        int bb = t >> 2, q = t & 3;
#pragma unroll
        for (int nn = 0; nn < NW; nn++) {
            float v[4];
#pragma unroll
            for (int e = 0; e < 4; e++)
                v[e] = red[(0 * 4 + q) * 1024 + bb * 16 + nn * 4 + e]
                     + red[(1 * 4 + q) * 1024 + bb * 16 + nn * 4 + e];
            *(float4*)&g_part[(((size_t)s * N2 + n0 + nn) * BATCH + bb) * DDIM + q * 4] =
                make_float4(v[0], v[1], v[2], v[3]);
        }
    }
}

// =====================================================================
// K2 (fused K1-reduce): v0 for 4 n's into smem [nn][d][b], then
// raw[n][i][b] = sum_p x[b,i,p] * ( sum_d v0[n,b,d] W[i,n,d,p] )
// warp w -> il = w
// =====================================================================
__global__ void __launch_bounds__(256, 2) cap_k2(const float* __restrict__ x,
                                                 const float* __restrict__ W) {
    extern __shared__ float sm[];
    __shared__ __align__(8) ull mbars[2];
    float* v0s = sm + 2 * STAGE_F;       // [nn][d][b] 4096 f
    const int n0 = blockIdx.x * NW, s = blockIdx.y;
    const int t = threadIdx.x, w = t >> 5, lane = t & 31;
    const int b0 = lane, b1 = lane + 32;
    const int ib = s * ISL;
    const uint32_t sbase = (uint32_t)__cvta_generic_to_shared(sm);
    const uint32_t mb[2] = { (uint32_t)__cvta_generic_to_shared(&mbars[0]),
                             (uint32_t)__cvta_generic_to_shared(&mbars[1]) };

    if (t == 0) { mbar_init(mb[0], 8); mbar_init(mb[1], 8); }

    // ---- fused K1 reduce into sm temp [nn][b][d] ----
    {
        int bb = t >> 2, q = t & 3;
#pragma unroll
        for (int nn = 0; nn < NW; nn++) {
            float4 v = make_float4(0.f, 0.f, 0.f, 0.f);
            for (int sl = 0; sl < SLICES; sl++) {
                float4 p = *(const float4*)&g_part[(((size_t)sl * N2 + n0 + nn) * BATCH + bb) * DDIM + q * 4];
                v.x += p.x; v.y += p.y; v.z += p.z; v.w += p.w;
            }
            *(float4*)&sm[(nn * BATCH + bb) * DDIM + q * 4] = v;
        }
    }
    __syncthreads();
    {   // squash + transpose: t -> nn = t>>6, b = t&63
        int nn = t >> 6, b = t & 63;
        float sv[16], sq = 0.f;
#pragma unroll
        for (int d = 0; d < 16; d++) {
            float v = sm[(nn * BATCH + b) * DDIM + d] * (1.f / 128.f);
            sv[d] = v; sq += v * v;
        }
        float f = sq / ((1.f + sq) * sqrtf(sq + EPSF));
        __syncthreads();
#pragma unroll
        for (int d = 0; d < 16; d++)
            v0s[(nn * DDIM + d) * BATCH + b] = f * sv[d];
    }
    __syncthreads();

    tile_load(sbase, mb[0], x, W, n0, ib, t);

    for (int tt = 0; tt < TILES; tt++) {
        mbar_wait(mb[tt & 1], (tt >> 1) & 1);
        __syncthreads();
        if (tt + 1 < TILES)
            tile_load(sbase + ((tt + 1) & 1) * STAGE_F * 4, mb[(tt + 1) & 1],
                      x, W, n0, ib + (tt + 1) * IL, t);

        const float* wsb = sm + (tt & 1) * STAGE_F;
        const float* xsb = wsb + WS_F;
        const int i = ib + tt * IL + w;
        ulonglong2 xA01 = *(const ulonglong2*)&xsb[b0 * XROW + w * 8];
        ulonglong2 xA23 = *(const ulonglong2*)&xsb[b0 * XROW + w * 8 + 4];
        ulonglong2 xB01 = *(const ulonglong2*)&xsb[b1 * XROW + w * 8];
        ulonglong2 xB23 = *(const ulonglong2*)&xsb[b1 * XROW + w * 8 + 4];

#pragma unroll
        for (int nn = 0; nn < NW; nn++) {
            const ulonglong2* wv = (const ulonglong2*)&wsb[(w * NW + nn) * 128];
            ull tA0 = 0, tA1 = 0, tA2 = 0, tA3 = 0;
            ull tB0 = 0, tB1 = 0, tB2 = 0, tB3 = 0;
#pragma unroll
            for (int d = 0; d < 16; d++) {
                float uA = v0s[(nn * DDIM + d) * BATCH + b0];
                float uB = v0s[(nn * DDIM + d) * BATCH + b1];
                ull u2A = pack2(uA, uA);
                ull u2B = pack2(uB, uB);
                ulonglong2 w01 = wv[2 * d], w23 = wv[2 * d + 1];
                tA0 = ffma2(u2A, w01.x, tA0);
                tA1 = ffma2(u2A, w01.y, tA1);
                tA2 = ffma2(u2A, w23.x, tA2);
                tA3 = ffma2(u2A, w23.y, tA3);
                tB0 = ffma2(u2B, w01.x, tB0);
                tB1 = ffma2(u2B, w01.y, tB1);
                tB2 = ffma2(u2B, w23.x, tB2);
                tB3 = ffma2(u2B, w23.y, tB3);
            }
            ull rA = fmul2(xA01.x, tA0);
            rA = ffma2(xA01.y, tA1, rA);
            rA = ffma2(xA23.x, tA2, rA);
            rA = ffma2(xA23.y, tA3, rA);
            ull rB = fmul2(xB01.x, tB0);
            rB = ffma2(xB01.y, tB1, rB);
            rB = ffma2(xB23.x, tB2, rB);
            rB = ffma2(xB23.y, tB3, rB);
            g_raw[(size_t)(n0 + nn) * BI + (size_t)i * BATCH + b0] = hadd2(rA);
            g_raw[(size_t)(n0 + nn) * BI + (size_t)i * BATCH + b1] = hadd2(rB);
        }
    }
}

// =====================================================================
// K3: per (b,i): s = sum_n exp(raw); then IN-PLACE raw <- c = exp(raw)/s
// (shift-free; raw bounded, softmax shift-invariant; column j is owned
// by one thread so in-place is race-free)
// =====================================================================
__global__ void __launch_bounds__(256) cap_k3() {
    const int j = blockIdx.x * 256 + threadIdx.x;   // j = i*64 + b
    float s0 = 0.f, s1 = 0.f;
#pragma unroll 8
    for (int n = 0; n < N2; n += 2) {
        s0 += __expf(g_raw[(size_t)n * BI + j]);
        s1 += __expf(g_raw[(size_t)(n + 1) * BI + j]);
    }
    const float inv = 1.f / (s0 + s1);
#pragma unroll 8
    for (int n = 0; n < N2; n++) {
        float r = g_raw[(size_t)n * BI + j];
        g_raw[(size_t)n * BI + j] = __expf(r) * inv;
    }
}

// =====================================================================
// K4 partial: part[s][n0+nn][b][d] = sum_{i in slice} c * pred
// (c read directly from g_raw — precomputed by k3)
// =====================================================================
__global__ void __launch_bounds__(256, 2) cap_k4p(const float* __restrict__ x,
                                                  const float* __restrict__ W) {
    extern __shared__ float sm[];
    __shared__ __align__(8) ull mbars[2];
    const int n0 = blockIdx.x * NW, s = blockIdx.y;
    const int t = threadIdx.x, w = t >> 5, lane = t & 31;
    const int dq = w & 3, ilh = w >> 2;
    const int b0 = lane, b1 = lane + 32;
    const int ib = s * ISL;
    const uint32_t sbase = (uint32_t)__cvta_generic_to_shared(sm);
    const uint32_t mb[2] = { (uint32_t)__cvta_generic_to_shared(&mbars[0]),
                             (uint32_t)__cvta_generic_to_shared(&mbars[1]) };

    if (t == 0) { mbar_init(mb[0], 8); mbar_init(mb[1], 8); }
    __syncthreads();

    ull accA[NW][4], accB[NW][4];
#pragma unroll
    for (int nn = 0; nn < NW; nn++)
#pragma unroll
        for (int e = 0; e < 4; e++) { accA[nn][e] = 0ULL; accB[nn][e] = 0ULL; }

    tile_load(sbase, mb[0], x, W, n0, ib, t);

    for (int tt = 0; tt < TILES; tt++) {
        mbar_wait(mb[tt & 1], (tt >> 1) & 1);
        __syncthreads();
        if (tt + 1 < TILES)
            tile_load(sbase + ((tt + 1) & 1) * STAGE_F * 4, mb[(tt + 1) & 1],
                      x, W, n0, ib + (tt + 1) * IL, t);

        const float* wsb = sm + (tt & 1) * STAGE_F;
        const float* xsb = wsb + WS_F;
#pragma unroll
        for (int ii = 0; ii < 4; ii++) {
            const int il = ilh * 4 + ii;
            const int i = ib + tt * IL + il;
            ulonglong2 xA01 = *(const ulonglong2*)&xsb[b0 * XROW + il * 8];
            ulonglong2 xA23 = *(const ulonglong2*)&xsb[b0 * XROW + il * 8 + 4];
            ulonglong2 xB01 = *(const ulonglong2*)&xsb[b1 * XROW + il * 8];
            ulonglong2 xB23 = *(const ulonglong2*)&xsb[b1 * XROW + il * 8 + 4];
#pragma unroll
            for (int nn = 0; nn < NW; nn++) {
                float cA = g_raw[(size_t)(n0 + nn) * BI + (size_t)i * BATCH + b0];
                float cB = g_raw[(size_t)(n0 + nn) * BI + (size_t)i * BATCH + b1];
                ull c2A = pack2(cA, cA);
                ull c2B = pack2(cB, cB);
                ull xa0 = fmul2(c2A, xA01.x), xa1 = fmul2(c2A, xA01.y);
                ull xa2 = fmul2(c2A, xA23.x), xa3 = fmul2(c2A, xA23.y);
                ull xb0 = fmul2(c2B, xB01.x), xb1 = fmul2(c2B, xB01.y);
                ull xb2 = fmul2(c2B, xB23.x), xb3 = fmul2(c2B, xB23.y);
                const ulonglong2* wv =
                    (const ulonglong2*)&wsb[(il * NW + nn) * 128 + dq * 32];
#pragma unroll
                for (int e = 0; e < 4; e++) {
                    ulonglong2 w01 = wv[2 * e], w23 = wv[2 * e + 1];
                    accA[nn][e] = ffma2(w01.x, xa0, accA[nn][e]);
                    accA[nn][e] = ffma2(w01.y, xa1, accA[nn][e]);
                    accA[nn][e] = ffma2(w23.x, xa2, accA[nn][e]);
                    accA[nn][e] = ffma2(w23.y, xa3, accA[nn][e]);
                    accB[nn][e] = ffma2(w01.x, xb0, accB[nn][e]);
                    accB[nn][e] = ffma2(w01.y, xb1, accB[nn][e]);
                    accB[nn][e] = ffma2(w23.x, xb2, accB[nn][e]);
                    accB[nn][e] = ffma2(w23.y, xb3, accB[nn][e]);
                }
            }
        }
    }

    __syncthreads();
    float* red = sm;
#pragma unroll
    for (int nn = 0; nn < NW; nn++)
#pragma unroll
        for (int e = 0; e < 4; e++) {
            red[w * 1024 + b0 * 16 + nn * 4 + e] = hadd2(accA[nn][e]);
            red[w * 1024 + b1 * 16 + nn * 4 + e] = hadd2(accB[nn][e]);
        }
    __syncthreads();
    {
        int bb = t >> 2, q = t & 3;
#pragma unroll
        for (int nn = 0; nn < NW; nn++) {
            float v[4];
#pragma unroll
            for (int e = 0; e < 4; e++)
                v[e] = red[(0 * 4 + q) * 1024 + bb * 16 + nn * 4 + e]
                     + red[(1 * 4 + q) * 1024 + bb * 16 + nn * 4 + e];
            *(float4*)&g_part[(((size_t)s * N2 + n0 + nn) * BATCH + bb) * DDIM + q * 4] =
                make_float4(v[0], v[1], v[2], v[3]);
        }
    }
}

// =====================================================================
// K4 reduce: out[b][n][d] = squash_d( sum_s part[s][n][b][d] )
// =====================================================================
__global__ void __launch_bounds__(64) cap_k4r(float* __restrict__ out) {
    const int n = blockIdx.x, b = threadIdx.x;
    float sv[16];
#pragma unroll
    for (int d = 0; d < 16; d++) sv[d] = 0.f;
    for (int sl = 0; sl < SLICES; sl++) {
        const float4* p = (const float4*)&g_part[(((size_t)sl * N2 + n) * BATCH + b) * DDIM];
#pragma unroll
        for (int q = 0; q < 4; q++) {
            float4 v = p[q];
            sv[4 * q + 0] += v.x; sv[4 * q + 1] += v.y;
            sv[4 * q + 2] += v.z; sv[4 * q + 3] += v.w;
        }
    }
    float sq = 0.f;
#pragma unroll
    for (int d = 0; d < 16; d++) sq += sv[d] * sv[d];
    float f = sq / ((1.f + sq) * sqrtf(sq + EPSF));
    float4* o = (float4*)&out[((size_t)b * N2 + n) * DDIM];
#pragma unroll
    for (int q = 0; q < 4; q++)
        o[q] = make_float4(f * sv[4 * q], f * sv[4 * q + 1],
                           f * sv[4 * q + 2], f * sv[4 * q + 3]);
}

// =====================================================================
extern "C" void kernel_launch(void* const* d_in, const int* in_sizes, int n_in,
                              void* d_out, int out_size) {
    const float* x = (const float*)d_in[0];
    const float* W = (const float*)d_in[1];
    if (n_in >= 2 && in_sizes[0] > in_sizes[1]) {
        const float* tmp = x; x = W; W = tmp;
    }
    float* out = (float*)d_out;

    cudaFuncSetAttribute(cap_k1p, cudaFuncAttributeMaxDynamicSharedMemorySize, SM_MAIN);
    cudaFuncSetAttribute(cap_k2,  cudaFuncAttributeMaxDynamicSharedMemorySize, SM_K2);
    cudaFuncSetAttribute(cap_k4p, cudaFuncAttributeMaxDynamicSharedMemorySize, SM_MAIN);

    dim3 g(NBLK, SLICES);
    cap_k1p<<<g, 256, SM_MAIN>>>(x, W);
    cap_k2 <<<g, 256, SM_K2 >>>(x, W);
    cap_k3 <<<BI / 256, 256>>>();
    cap_k4p<<<g, 256, SM_MAIN>>>(x, W);
    cap_k4r<<<N2, 64>>>(out);
}